// round 1
// baseline (speedup 1.0000x reference)
#include <cuda_runtime.h>
#include <cstdint>

// ---------------------------------------------------------------------------
// StockModel: T=4, N=500, E=16, K=32, H=32, D=768, ZD=800, EH=200
//
// Pipeline:
//  K1  lstm1:  prices (T,N,1) -> p_seq (T,N,32)            [warp per stock]
//  K2  gemm:   GP = node_embs(2000x768) @ [W1b | Wih2b](768x328)
//              (G = cols 0..199, P = cols 200..327)         [32x32 tiled]
//  K3  edge:   per (t,n): gather region, vertex-conv attention,
//              vc, per-edge score s_e = W2·relu(G + vc@W1a^T + b1) + b2,
//              att = softmax_e, outputs hgv (32) and hgP (128)
//  K4  lstm2+heads: (hgv,hgP) -> h_n -> out (N,2)           [warp per stock]
// ---------------------------------------------------------------------------

#define TT 4
#define NS 500
#define EE 16
#define KK 32
#define HH 32
#define DD 768
#define ZDIM 800
#define EHID 200
#define GPW 328          // 200 (G) + 128 (P)
#define TN 2000          // T*N

__device__ float d_pseq[TN * HH];     // (t*N+n)*32 + h
__device__ float d_GP[TN * GPW];      // (t*N+node)*328 + col
__device__ float d_hgv[TN * HH];
__device__ float d_hgP[TN * 128];

__device__ __forceinline__ float sigf(float x) { return 1.0f / (1.0f + __expf(-x)); }

// ===========================================================================
// K1: price LSTM, one warp per stock. lane j owns h[j], c[j].
// ===========================================================================
__global__ __launch_bounds__(256) void k_lstm1(
    const float* __restrict__ prices,
    const float* __restrict__ Wih, const float* __restrict__ Whh,
    const float* __restrict__ bih, const float* __restrict__ bhh)
{
    int warp = (blockIdx.x * blockDim.x + threadIdx.x) >> 5;
    int lane = threadIdx.x & 31;
    if (warp >= NS) return;
    int n = warp;

    float wxi = Wih[lane],      wxf = Wih[32 + lane];
    float wxg = Wih[64 + lane], wxo = Wih[96 + lane];
    float bi = bih[lane]      + bhh[lane];
    float bf = bih[32 + lane] + bhh[32 + lane];
    float bg = bih[64 + lane] + bhh[64 + lane];
    float bo = bih[96 + lane] + bhh[96 + lane];

    float whi[32], whf[32], whg[32], who[32];
#pragma unroll
    for (int l = 0; l < 32; l++) {
        whi[l] = Whh[lane * 32 + l];
        whf[l] = Whh[(32 + lane) * 32 + l];
        whg[l] = Whh[(64 + lane) * 32 + l];
        who[l] = Whh[(96 + lane) * 32 + l];
    }

    float h = 0.0f, c = 0.0f;
#pragma unroll
    for (int t = 0; t < TT; t++) {
        float x = prices[t * NS + n];
        float zi = fmaf(wxi, x, bi), zf = fmaf(wxf, x, bf);
        float zg = fmaf(wxg, x, bg), zo = fmaf(wxo, x, bo);
#pragma unroll
        for (int l = 0; l < 32; l++) {
            float hl = __shfl_sync(0xffffffffu, h, l);
            zi = fmaf(whi[l], hl, zi);
            zf = fmaf(whf[l], hl, zf);
            zg = fmaf(whg[l], hl, zg);
            zo = fmaf(who[l], hl, zo);
        }
        c = sigf(zf) * c + sigf(zi) * tanhf(zg);
        h = sigf(zo) * tanhf(c);
        d_pseq[(t * NS + n) * HH + lane] = h;
    }
}

// ===========================================================================
// K2: GP = node_embs (2000x768) @ B (768x328)
//     B[d][col] = col<200 ? W1[col][32+d] : Wih2[col-200][32+d]
// 32x32 output tile, BK=32, 256 threads, 4 outputs/thread.
// ===========================================================================
__global__ __launch_bounds__(256) void k_gemm_gp(
    const float* __restrict__ ne,
    const float* __restrict__ W1,
    const float* __restrict__ Wih2)
{
    __shared__ float As[32][33];
    __shared__ float Bs[32][33];
    int rb = blockIdx.x * 32, cb = blockIdx.y * 32;
    int tid = threadIdx.x;
    int r  = tid & 31;     // output row in tile
    int cg = tid >> 5;     // 0..7
    float acc0 = 0.f, acc1 = 0.f, acc2 = 0.f, acc3 = 0.f;

    for (int k0 = 0; k0 < DD; k0 += 32) {
#pragma unroll
        for (int q = 0; q < 4; q++) {
            int idx = tid + q * 256;
            int i = idx >> 5, j = idx & 31;
            int row = rb + i;
            As[i][j] = (row < TN) ? ne[row * DD + k0 + j] : 0.0f;
            // B load, coalesced along d: thread maps (c = i, d = j)
            int col = cb + i;
            int dglob = k0 + j;
            float b;
            if (col < 200)       b = W1[col * ZDIM + 32 + dglob];
            else if (col < GPW)  b = Wih2[(col - 200) * ZDIM + 32 + dglob];
            else                 b = 0.0f;
            Bs[j][i] = b;   // Bs[k][col]
        }
        __syncthreads();
#pragma unroll
        for (int k = 0; k < 32; k++) {
            float a = As[r][k];
            acc0 = fmaf(a, Bs[k][cg],      acc0);
            acc1 = fmaf(a, Bs[k][cg + 8],  acc1);
            acc2 = fmaf(a, Bs[k][cg + 16], acc2);
            acc3 = fmaf(a, Bs[k][cg + 24], acc3);
        }
        __syncthreads();
    }
    int row = rb + r;
    if (row < TN) {
        int c0 = cb + cg;
        if (c0 < GPW)      d_GP[row * GPW + c0]      = acc0;
        if (c0 + 8 < GPW)  d_GP[row * GPW + c0 + 8]  = acc1;
        if (c0 + 16 < GPW) d_GP[row * GPW + c0 + 16] = acc2;
        if (c0 + 24 < GPW) d_GP[row * GPW + c0 + 24] = acc3;
    }
}

// ===========================================================================
// K3: fused VertexConv + EdgeConv per (t,n). 2000 blocks x 256 threads.
// ===========================================================================
__global__ __launch_bounds__(256) void k_edge(
    const int* __restrict__ adj, const int* __restrict__ mem,
    const float* __restrict__ Wt, const float* __restrict__ bt,
    const float* __restrict__ wk, const float* __restrict__ bk,
    const float* __restrict__ W1, const float* __restrict__ b1,
    const float* __restrict__ W2, const float* __restrict__ b2)
{
    extern __shared__ float sm[];
    float* region = sm;                      // [e][k][d] 16*32*32 = 16384
    float* Mbuf   = region + 16384;          // [e*32+i][j] stride 33 -> 16896
    float* alpha  = Mbuf + 16896;            // [e][j] 512
    float* vc     = alpha + 512;             // [e][d] 512
    float* svals  = vc + 512;                // 16
    float* satt   = svals + 16;              // 16
    int*   sadj   = (int*)(satt + 16);       // 16
    int*   midx   = sadj + 16;               // 512

    int tid = threadIdx.x;
    int bid = blockIdx.x;       // t*N + n
    int tN  = (bid / NS) * NS;  // t*N

    if (tid < EE) sadj[tid] = adj[bid * EE + tid];
    __syncthreads();

    for (int q = tid; q < EE * KK; q += 256) {
        int e = q >> 5;
        midx[q] = mem[(tN + sadj[e]) * KK + (q & 31)];
    }
    __syncthreads();

    // gather region[e][k][:] = p_seq[t, midx[e][k], :]
    for (int q = tid; q < EE * KK * HH; q += 256) {
        int ek = q >> 5;
        region[q] = d_pseq[(tN + midx[ek]) * HH + (q & 31)];
    }
    __syncthreads();

    // M[e][i][j] = region[e][i][:] . Wt[i][j][:] + bt[i][j]
    // thread owns (i,j) pairs; Wt row cached in registers, reused across e.
    for (int p = tid; p < KK * KK; p += 256) {
        float w[32];
        const float4* wt4 = (const float4*)(Wt + p * 32);
#pragma unroll
        for (int q4 = 0; q4 < 8; q4++) {
            float4 v = wt4[q4];
            w[q4 * 4] = v.x; w[q4 * 4 + 1] = v.y; w[q4 * 4 + 2] = v.z; w[q4 * 4 + 3] = v.w;
        }
        float bij = bt[p];
        int i = p >> 5, j = p & 31;
#pragma unroll
        for (int e = 0; e < EE; e++) {
            const float* rg = region + e * 1024 + i * 32;
            float acc = bij;
#pragma unroll
            for (int d = 0; d < 32; d++) acc = fmaf(w[d], rg[d], acc);
            Mbuf[(e * 32 + i) * 33 + j] = acc;
        }
    }
    __syncthreads();

    // softmax over j for each of the 512 rows
    for (int rI = tid; rI < EE * KK; rI += 256) {
        float* row = Mbuf + rI * 33;
        float mx = row[0];
#pragma unroll
        for (int j = 1; j < 32; j++) mx = fmaxf(mx, row[j]);
        float ssum = 0.0f;
#pragma unroll
        for (int j = 0; j < 32; j++) { float v = __expf(row[j] - mx); row[j] = v; ssum += v; }
        float inv = 1.0f / ssum;
#pragma unroll
        for (int j = 0; j < 32; j++) row[j] *= inv;
    }
    __syncthreads();

    // alpha[e][j] = sum_k wk[k] * mult[e][k][j]
    for (int q = tid; q < EE * KK; q += 256) {
        int e = q >> 5, j = q & 31;
        float acc = 0.0f;
#pragma unroll
        for (int k = 0; k < 32; k++) acc = fmaf(__ldg(wk + k), Mbuf[(e * 32 + k) * 33 + j], acc);
        alpha[q] = acc;
    }
    __syncthreads();

    // vc[e][d] = bk + sum_j alpha[e][j] * region[e][j][d]
    float bk0 = __ldg(bk);
    for (int q = tid; q < EE * KK; q += 256) {
        int e = q >> 5, d = q & 31;
        float acc = bk0;
#pragma unroll
        for (int j = 0; j < 32; j++) acc = fmaf(alpha[e * 32 + j], region[e * 1024 + j * 32 + d], acc);
        vc[q] = acc;
    }
    __syncthreads();

    // s_e = b2 + sum_m W2[m] * relu(b1[m] + G[t,a_e,m] + vc_e . W1[m,:32])
    // 8 threads per edge, 25 m's each; reduce within 8-lane groups.
    if (tid < 128) {
        int e = tid >> 3, q = tid & 7;
        const float* vce = vc + e * 32;
        const float* Grow = d_GP + (tN + sadj[e]) * GPW;
        float partial = 0.0f;
        for (int m = q * 25; m < q * 25 + 25; m++) {
            float acc = b1[m] + Grow[m];
            const float4* w4 = (const float4*)(W1 + m * ZDIM);
#pragma unroll
            for (int dq = 0; dq < 8; dq++) {
                float4 v = w4[dq];
                acc = fmaf(v.x, vce[dq * 4],     acc);
                acc = fmaf(v.y, vce[dq * 4 + 1], acc);
                acc = fmaf(v.z, vce[dq * 4 + 2], acc);
                acc = fmaf(v.w, vce[dq * 4 + 3], acc);
            }
            acc = fmaxf(acc, 0.0f);
            partial = fmaf(W2[m], acc, partial);
        }
        partial += __shfl_xor_sync(0xffffffffu, partial, 1);
        partial += __shfl_xor_sync(0xffffffffu, partial, 2);
        partial += __shfl_xor_sync(0xffffffffu, partial, 4);
        if (q == 0) svals[e] = partial + __ldg(b2);
    }
    __syncthreads();

    // att = softmax over edges
    if (tid == 0) {
        float mx = svals[0];
#pragma unroll
        for (int e = 1; e < EE; e++) mx = fmaxf(mx, svals[e]);
        float ssum = 0.0f;
#pragma unroll
        for (int e = 0; e < EE; e++) { float v = __expf(svals[e] - mx); satt[e] = v; ssum += v; }
        float inv = 1.0f / ssum;
#pragma unroll
        for (int e = 0; e < EE; e++) satt[e] *= inv;
    }
    __syncthreads();

    // hgv[d] = sum_e att_e * vc[e][d]   (first 32 dims of hg)
    if (tid < 32) {
        float acc = 0.0f;
#pragma unroll
        for (int e = 0; e < EE; e++) acc = fmaf(satt[e], vc[e * 32 + tid], acc);
        d_hgv[bid * HH + tid] = acc;
    }
    // hgP[g] = sum_e att_e * P[t,a_e,g]  (hg[32:800] @ Wih2b^T, pre-projected)
    if (tid < 128) {
        float acc = 0.0f;
#pragma unroll
        for (int e = 0; e < EE; e++)
            acc = fmaf(satt[e], d_GP[(tN + sadj[e]) * GPW + 200 + tid], acc);
        d_hgP[bid * 128 + tid] = acc;
    }
}

// ===========================================================================
// K4: second LSTM (+heads), one warp per stock.
// gate(g) = bih2[g]+bhh2[g] + hgP[g] + sum_d Wih2[g][d]*hgv[d] + sum_l Whh2[g][l]*h[l]
// ===========================================================================
__global__ __launch_bounds__(256) void k_lstm2(
    const float* __restrict__ Wih2, const float* __restrict__ Whh2,
    const float* __restrict__ bih2, const float* __restrict__ bhh2,
    const float* __restrict__ Wf1, const float* __restrict__ bf1,
    const float* __restrict__ Wf2, const float* __restrict__ bf2,
    float* __restrict__ out)
{
    int warp = (blockIdx.x * blockDim.x + threadIdx.x) >> 5;
    int lane = threadIdx.x & 31;
    if (warp >= NS) return;
    int n = warp;

    float bi = bih2[lane]      + bhh2[lane];
    float bf = bih2[32 + lane] + bhh2[32 + lane];
    float bg = bih2[64 + lane] + bhh2[64 + lane];
    float bo = bih2[96 + lane] + bhh2[96 + lane];

    float whi[32], whf[32], whg[32], who[32];
#pragma unroll
    for (int l = 0; l < 32; l++) {
        whi[l] = Whh2[lane * 32 + l];
        whf[l] = Whh2[(32 + lane) * 32 + l];
        whg[l] = Whh2[(64 + lane) * 32 + l];
        who[l] = Whh2[(96 + lane) * 32 + l];
    }

    float h = 0.0f, c = 0.0f;
    for (int t = 0; t < TT; t++) {
        int row = t * NS + n;
        float hvv = d_hgv[row * HH + lane];
        const float* hp = d_hgP + row * 128;
        float zi = bi + hp[lane];
        float zf = bf + hp[32 + lane];
        float zg = bg + hp[64 + lane];
        float zo = bo + hp[96 + lane];
#pragma unroll
        for (int l = 0; l < 32; l++) {
            float hl  = __shfl_sync(0xffffffffu, h,   l);
            float hvl = __shfl_sync(0xffffffffu, hvv, l);
            zi = fmaf(whi[l], hl, zi);
            zf = fmaf(whf[l], hl, zf);
            zg = fmaf(whg[l], hl, zg);
            zo = fmaf(who[l], hl, zo);
            zi = fmaf(__ldg(Wih2 + lane * ZDIM + l), hvl, zi);
            zf = fmaf(__ldg(Wih2 + (32 + lane) * ZDIM + l), hvl, zf);
            zg = fmaf(__ldg(Wih2 + (64 + lane) * ZDIM + l), hvl, zg);
            zo = fmaf(__ldg(Wih2 + (96 + lane) * ZDIM + l), hvl, zo);
        }
        c = sigf(zf) * c + sigf(zi) * tanhf(zg);
        h = sigf(zo) * tanhf(c);
    }

    // heads: f1 = h @ Wf1^T + bf1 (64), out = f1 @ Wf2^T + bf2 (2). No activation.
    float f1a = bf1[lane], f1b = bf1[32 + lane];
#pragma unroll
    for (int l = 0; l < 32; l++) {
        float hl = __shfl_sync(0xffffffffu, h, l);
        f1a = fmaf(Wf1[lane * 32 + l], hl, f1a);
        f1b = fmaf(Wf1[(32 + lane) * 32 + l], hl, f1b);
    }
    float p0 = Wf2[lane] * f1a + Wf2[32 + lane] * f1b;
    float p1 = Wf2[64 + lane] * f1a + Wf2[96 + lane] * f1b;
#pragma unroll
    for (int off = 16; off > 0; off >>= 1) {
        p0 += __shfl_xor_sync(0xffffffffu, p0, off);
        p1 += __shfl_xor_sync(0xffffffffu, p1, off);
    }
    if (lane == 0) {
        out[n * 2]     = p0 + bf2[0];
        out[n * 2 + 1] = p1 + bf2[1];
    }
}

// ===========================================================================
extern "C" void kernel_launch(void* const* d_in, const int* in_sizes, int n_in,
                              void* d_out, int out_size)
{
    const float* prices    = (const float*)d_in[0];
    const float* node_embs = (const float*)d_in[1];
    const int*   adj       = (const int*)  d_in[2];
    const int*   mem       = (const int*)  d_in[3];
    const float* W_ih1 = (const float*)d_in[4];
    const float* W_hh1 = (const float*)d_in[5];
    const float* b_ih1 = (const float*)d_in[6];
    const float* b_hh1 = (const float*)d_in[7];
    const float* Wt    = (const float*)d_in[8];
    const float* bt    = (const float*)d_in[9];
    const float* wk    = (const float*)d_in[10];
    const float* bk    = (const float*)d_in[11];
    const float* W1    = (const float*)d_in[12];
    const float* b1    = (const float*)d_in[13];
    const float* W2    = (const float*)d_in[14];
    const float* b2    = (const float*)d_in[15];
    const float* W_ih2 = (const float*)d_in[16];
    const float* W_hh2 = (const float*)d_in[17];
    const float* b_ih2 = (const float*)d_in[18];
    const float* b_hh2 = (const float*)d_in[19];
    const float* Wf1   = (const float*)d_in[20];
    const float* bf1   = (const float*)d_in[21];
    const float* Wf2   = (const float*)d_in[22];
    const float* bf2   = (const float*)d_in[23];
    float* out = (float*)d_out;

    // smem for k_edge: 34336 floats + 528 ints
    const int edge_smem = (16384 + 16896 + 512 + 512 + 16 + 16) * 4 + (16 + 512) * 4;
    cudaFuncSetAttribute(k_edge, cudaFuncAttributeMaxDynamicSharedMemorySize, edge_smem);

    k_lstm1<<<63, 256>>>(prices, W_ih1, W_hh1, b_ih1, b_hh1);
    dim3 ggrid((TN + 31) / 32, (GPW + 31) / 32);
    k_gemm_gp<<<ggrid, 256>>>(node_embs, W1, W_ih2);
    k_edge<<<TN, 256, edge_smem>>>(adj, mem, Wt, bt, wk, bk, W1, b1, W2, b2);
    k_lstm2<<<63, 256>>>(W_ih2, W_hh2, b_ih2, b_hh2, Wf1, bf1, Wf2, bf2, out);
}

// round 3
// speedup vs baseline: 1.4753x; 1.4753x over previous
#include <cuda_runtime.h>
#include <cstdint>

// ---------------------------------------------------------------------------
// StockModel: T=4, N=500, E=16, K=32, H=32, D=768, ZD=800, EH=200
//
//  K1  lstm1:  prices (T,N,1) -> p_seq (T,N,32)             [warp/stock]
//  K2  gemm:   GP = node_embs(2000x768) @ [W1b | Wih2b](768x328)
//  K3  edge:   per (t,n): gather, vertex-conv attn (register softmax),
//              vc, edge scores, att-softmax, outputs hgX = hgP + Wih2a@hgv
//  K4  lstm2+heads: hgX -> h_n -> out (N,2)                 [warp/stock]
// ---------------------------------------------------------------------------

#define TT 4
#define NS 500
#define EE 16
#define KK 32
#define HH 32
#define DD 768
#define ZDIM 800
#define GPW 328          // 200 (G) + 128 (P)
#define TN 2000          // T*N

__device__ float d_pseq[TN * HH];
__device__ float d_GP[TN * GPW];
__device__ float d_hgX[TN * 128];

__device__ __forceinline__ float sigf(float x) { return 1.0f / (1.0f + __expf(-x)); }

// ===========================================================================
// K1: price LSTM, one warp per stock.
// ===========================================================================
__global__ __launch_bounds__(128) void k_lstm1(
    const float* __restrict__ prices,
    const float* __restrict__ Wih, const float* __restrict__ Whh,
    const float* __restrict__ bih, const float* __restrict__ bhh)
{
    int warp = (blockIdx.x * blockDim.x + threadIdx.x) >> 5;
    int lane = threadIdx.x & 31;
    if (warp >= NS) return;
    int n = warp;

    float wxi = Wih[lane],      wxf = Wih[32 + lane];
    float wxg = Wih[64 + lane], wxo = Wih[96 + lane];
    float bi = bih[lane]      + bhh[lane];
    float bf = bih[32 + lane] + bhh[32 + lane];
    float bg = bih[64 + lane] + bhh[64 + lane];
    float bo = bih[96 + lane] + bhh[96 + lane];

    float whi[32], whf[32], whg[32], who[32];
#pragma unroll
    for (int l = 0; l < 32; l++) {
        whi[l] = Whh[lane * 32 + l];
        whf[l] = Whh[(32 + lane) * 32 + l];
        whg[l] = Whh[(64 + lane) * 32 + l];
        who[l] = Whh[(96 + lane) * 32 + l];
    }

    float h = 0.0f, c = 0.0f;
#pragma unroll
    for (int t = 0; t < TT; t++) {
        float x = prices[t * NS + n];
        float zi = fmaf(wxi, x, bi), zf = fmaf(wxf, x, bf);
        float zg = fmaf(wxg, x, bg), zo = fmaf(wxo, x, bo);
#pragma unroll
        for (int l = 0; l < 32; l++) {
            float hl = __shfl_sync(0xffffffffu, h, l);
            zi = fmaf(whi[l], hl, zi);
            zf = fmaf(whf[l], hl, zf);
            zg = fmaf(whg[l], hl, zg);
            zo = fmaf(who[l], hl, zo);
        }
        c = sigf(zf) * c + sigf(zi) * tanhf(zg);
        h = sigf(zo) * tanhf(c);
        d_pseq[(t * NS + n) * HH + lane] = h;
    }
}

// ===========================================================================
// K2: GP = node_embs (2000x768) @ B (768x328), 64x64 tile, BK=16, 4x4/thread
// ===========================================================================
__global__ __launch_bounds__(256) void k_gemm_gp(
    const float* __restrict__ ne,
    const float* __restrict__ W1,
    const float* __restrict__ Wih2)
{
    __shared__ float As[16][64];
    __shared__ float Bs[16][64];
    int rb = blockIdx.x * 64, cb = blockIdx.y * 64;
    int tid = threadIdx.x;
    int tx = tid & 15, ty = tid >> 4;
    int lm = tid >> 2;            // 0..63 (row/col within tile for loading)
    int lk = (tid & 3) * 4;       // k offset 0,4,8,12

    float acc[4][4];
#pragma unroll
    for (int r = 0; r < 4; r++)
#pragma unroll
        for (int cq = 0; cq < 4; cq++) acc[r][cq] = 0.0f;

    int arow = rb + lm;
    int bcol = cb + lm;

    for (int k0 = 0; k0 < DD; k0 += 16) {
        float4 av = make_float4(0.f, 0.f, 0.f, 0.f);
        if (arow < TN) av = *(const float4*)(ne + arow * DD + k0 + lk);
        float4 bv = make_float4(0.f, 0.f, 0.f, 0.f);
        if (bcol < 200)      bv = *(const float4*)(W1 + bcol * ZDIM + 32 + k0 + lk);
        else if (bcol < GPW) bv = *(const float4*)(Wih2 + (bcol - 200) * ZDIM + 32 + k0 + lk);
        As[lk + 0][lm] = av.x; As[lk + 1][lm] = av.y;
        As[lk + 2][lm] = av.z; As[lk + 3][lm] = av.w;
        Bs[lk + 0][lm] = bv.x; Bs[lk + 1][lm] = bv.y;
        Bs[lk + 2][lm] = bv.z; Bs[lk + 3][lm] = bv.w;
        __syncthreads();
#pragma unroll
        for (int k = 0; k < 16; k++) {
            float4 a4 = *(const float4*)(&As[k][ty * 4]);
            float4 b4 = *(const float4*)(&Bs[k][tx * 4]);
            float ar[4] = {a4.x, a4.y, a4.z, a4.w};
            float br[4] = {b4.x, b4.y, b4.z, b4.w};
#pragma unroll
            for (int r = 0; r < 4; r++)
#pragma unroll
                for (int cq = 0; cq < 4; cq++)
                    acc[r][cq] = fmaf(ar[r], br[cq], acc[r][cq]);
        }
        __syncthreads();
    }
#pragma unroll
    for (int r = 0; r < 4; r++) {
        int row = rb + ty * 4 + r;
        int col = cb + tx * 4;
        if (row < TN && col < GPW) {
            float4 v = make_float4(acc[r][0], acc[r][1], acc[r][2], acc[r][3]);
            *(float4*)(d_GP + row * GPW + col) = v;
        }
    }
}

// ===========================================================================
// K3: fused VertexConv + EdgeConv per (t,n). 2000 blocks x 256 threads.
// smem ~104.8KB -> 2 blocks/SM.
// ===========================================================================
__global__ __launch_bounds__(256) void k_edge(
    const int* __restrict__ adj, const int* __restrict__ mem,
    const float* __restrict__ Wt, const float* __restrict__ bt,
    const float* __restrict__ wk, const float* __restrict__ bk,
    const float* __restrict__ W1, const float* __restrict__ b1,
    const float* __restrict__ W2, const float* __restrict__ b2,
    const float* __restrict__ Wih2)
{
    extern __shared__ float sm[];
    float* region = sm;                  // [e][k][d] 16384
    float* wihAT  = region + 16384;      // [d][g]    4096
    float* apart  = wihAT + 4096;        // [w][e][j] 4096
    float* alpha  = apart + 4096;        // [e][j]    512
    float* vc     = alpha + 512;         // [e][d]    512
    float* hgv_s  = vc + 512;            // 32
    float* svals  = hgv_s + 32;          // 16
    float* satt   = svals + 16;          // 16
    int*   sadj   = (int*)(satt + 16);   // 16
    int*   midx   = sadj + 16;           // 512

    int tid = threadIdx.x, w = tid >> 5, lane = tid & 31;
    int bid = blockIdx.x;
    int tN  = (bid / NS) * NS;

    if (tid < EE) sadj[tid] = adj[bid * EE + tid];
    // stage Wih2[:, :32] transposed: wihAT[d*128+g]
    for (int idx = tid; idx < 4096; idx += 256) {
        int d = idx >> 7, g = idx & 127;
        wihAT[idx] = __ldg(Wih2 + g * ZDIM + d);
    }
    __syncthreads();

    for (int q = tid; q < EE * KK; q += 256)
        midx[q] = mem[(tN + sadj[q >> 5]) * KK + (q & 31)];
    __syncthreads();

    for (int q = tid; q < EE * KK * HH; q += 256)
        region[q] = d_pseq[(tN + midx[q >> 5]) * HH + (q & 31)];
    __syncthreads();

    // ---- VertexConv attention: row (e,i) softmax in registers, lane = j ----
    // alpha[e][j] = sum_i wk[i] * softmax_j(region[e,i,:].Wt[i,j,:] + bt[i,j])
    float accE[16];
#pragma unroll
    for (int e = 0; e < 16; e++) accE[e] = 0.0f;

#pragma unroll
    for (int ii = 0; ii < 4; ii++) {
        int i = w + ii * 8;
        const float4* wt4 = (const float4*)(Wt + (i * 32 + lane) * 32);
        float4 wr[8];
#pragma unroll
        for (int q = 0; q < 8; q++) wr[q] = wt4[q];
        float bij = __ldg(bt + i * 32 + lane);
        float wki = __ldg(wk + i);
#pragma unroll
        for (int e = 0; e < 16; e++) {
            const float4* rg = (const float4*)(region + e * 1024 + i * 32);
            float m = bij;
#pragma unroll
            for (int q = 0; q < 8; q++) {
                float4 r = rg[q];
                m = fmaf(wr[q].x, r.x, m);
                m = fmaf(wr[q].y, r.y, m);
                m = fmaf(wr[q].z, r.z, m);
                m = fmaf(wr[q].w, r.w, m);
            }
            float mx = m;
#pragma unroll
            for (int off = 16; off > 0; off >>= 1)
                mx = fmaxf(mx, __shfl_xor_sync(0xffffffffu, mx, off));
            float v = __expf(m - mx);
            float s = v;
#pragma unroll
            for (int off = 16; off > 0; off >>= 1)
                s += __shfl_xor_sync(0xffffffffu, s, off);
            accE[e] = fmaf(wki, __fdividef(v, s), accE[e]);
        }
    }
#pragma unroll
    for (int e = 0; e < 16; e++) apart[w * 512 + e * 32 + lane] = accE[e];
    __syncthreads();

    for (int q = tid; q < EE * KK; q += 256) {
        float a = 0.0f;
#pragma unroll
        for (int p = 0; p < 8; p++) a += apart[p * 512 + q];
        alpha[q] = a;
    }
    __syncthreads();

    // vc[e][d] = bk + sum_j alpha[e][j] * region[e][j][d]
    float bk0 = __ldg(bk);
    for (int q = tid; q < EE * KK; q += 256) {
        int e = q >> 5, d = q & 31;
        float acc = bk0;
#pragma unroll
        for (int j = 0; j < 32; j++)
            acc = fmaf(alpha[e * 32 + j], region[e * 1024 + j * 32 + d], acc);
        vc[q] = acc;
    }
    __syncthreads();

    // ---- edge scores: 16 threads/edge over m in [0,200) ----
    {
        int e = tid >> 4, q = tid & 15;
        const float* vce = vc + e * 32;
        const float* Grow = d_GP + (tN + sadj[e]) * GPW;
        float partial = 0.0f;
        for (int m = q; m < 200; m += 16) {
            float acc = __ldg(b1 + m) + Grow[m];
            const float4* w4 = (const float4*)(W1 + m * ZDIM);
#pragma unroll
            for (int dq = 0; dq < 8; dq++) {
                float4 v = w4[dq];
                acc = fmaf(v.x, vce[dq * 4],     acc);
                acc = fmaf(v.y, vce[dq * 4 + 1], acc);
                acc = fmaf(v.z, vce[dq * 4 + 2], acc);
                acc = fmaf(v.w, vce[dq * 4 + 3], acc);
            }
            partial = fmaf(__ldg(W2 + m), fmaxf(acc, 0.0f), partial);
        }
#pragma unroll
        for (int off = 8; off > 0; off >>= 1)
            partial += __shfl_xor_sync(0xffffffffu, partial, off);
        if (q == 0) svals[e] = partial + __ldg(b2);
    }
    __syncthreads();

    if (tid == 0) {
        float mx = svals[0];
#pragma unroll
        for (int e = 1; e < EE; e++) mx = fmaxf(mx, svals[e]);
        float s = 0.0f;
#pragma unroll
        for (int e = 0; e < EE; e++) { float v = __expf(svals[e] - mx); satt[e] = v; s += v; }
        float inv = 1.0f / s;
#pragma unroll
        for (int e = 0; e < EE; e++) satt[e] *= inv;
    }
    __syncthreads();

    if (tid < 32) {
        float acc = 0.0f;
#pragma unroll
        for (int e = 0; e < EE; e++) acc = fmaf(satt[e], vc[e * 32 + tid], acc);
        hgv_s[tid] = acc;
    }
    __syncthreads();

    // hgX[g] = sum_e att_e * P[t,a_e,g] + sum_d Wih2[g][d] * hgv[d]
    if (tid < 128) {
        int g = tid;
        float acc = 0.0f;
#pragma unroll
        for (int e = 0; e < EE; e++)
            acc = fmaf(satt[e], d_GP[(tN + sadj[e]) * GPW + 200 + g], acc);
#pragma unroll
        for (int d = 0; d < 32; d++)
            acc = fmaf(wihAT[d * 128 + g], hgv_s[d], acc);
        d_hgX[bid * 128 + g] = acc;
    }
}

// ===========================================================================
// K4: second LSTM + heads, one warp per stock. Input gates precomputed (hgX).
// ===========================================================================
__global__ __launch_bounds__(128) void k_lstm2(
    const float* __restrict__ Whh2,
    const float* __restrict__ bih2, const float* __restrict__ bhh2,
    const float* __restrict__ Wf1, const float* __restrict__ bf1,
    const float* __restrict__ Wf2, const float* __restrict__ bf2,
    float* __restrict__ out)
{
    int warp = (blockIdx.x * blockDim.x + threadIdx.x) >> 5;
    int lane = threadIdx.x & 31;
    if (warp >= NS) return;
    int n = warp;

    float bi = bih2[lane]      + bhh2[lane];
    float bf = bih2[32 + lane] + bhh2[32 + lane];
    float bg = bih2[64 + lane] + bhh2[64 + lane];
    float bo = bih2[96 + lane] + bhh2[96 + lane];

    float whi[32], whf[32], whg[32], who[32];
#pragma unroll
    for (int l = 0; l < 32; l++) {
        whi[l] = Whh2[lane * 32 + l];
        whf[l] = Whh2[(32 + lane) * 32 + l];
        whg[l] = Whh2[(64 + lane) * 32 + l];
        who[l] = Whh2[(96 + lane) * 32 + l];
    }

    float h = 0.0f, c = 0.0f;
#pragma unroll
    for (int t = 0; t < TT; t++) {
        const float* hx = d_hgX + (t * NS + n) * 128;
        float zi = bi + hx[lane];
        float zf = bf + hx[32 + lane];
        float zg = bg + hx[64 + lane];
        float zo = bo + hx[96 + lane];
#pragma unroll
        for (int l = 0; l < 32; l++) {
            float hl = __shfl_sync(0xffffffffu, h, l);
            zi = fmaf(whi[l], hl, zi);
            zf = fmaf(whf[l], hl, zf);
            zg = fmaf(whg[l], hl, zg);
            zo = fmaf(who[l], hl, zo);
        }
        c = sigf(zf) * c + sigf(zi) * tanhf(zg);
        h = sigf(zo) * tanhf(c);
    }

    float f1a = bf1[lane], f1b = bf1[32 + lane];
#pragma unroll
    for (int l = 0; l < 32; l++) {
        float hl = __shfl_sync(0xffffffffu, h, l);
        f1a = fmaf(Wf1[lane * 32 + l], hl, f1a);
        f1b = fmaf(Wf1[(32 + lane) * 32 + l], hl, f1b);
    }
    float p0 = Wf2[lane] * f1a + Wf2[32 + lane] * f1b;
    float p1 = Wf2[64 + lane] * f1a + Wf2[96 + lane] * f1b;
#pragma unroll
    for (int off = 16; off > 0; off >>= 1) {
        p0 += __shfl_xor_sync(0xffffffffu, p0, off);
        p1 += __shfl_xor_sync(0xffffffffu, p1, off);
    }
    if (lane == 0) {
        out[n * 2]     = p0 + bf2[0];
        out[n * 2 + 1] = p1 + bf2[1];
    }
}

// ===========================================================================
extern "C" void kernel_launch(void* const* d_in, const int* in_sizes, int n_in,
                              void* d_out, int out_size)
{
    const float* prices    = (const float*)d_in[0];
    const float* node_embs = (const float*)d_in[1];
    const int*   adj       = (const int*)  d_in[2];
    const int*   mem       = (const int*)  d_in[3];
    const float* W_ih1 = (const float*)d_in[4];
    const float* W_hh1 = (const float*)d_in[5];
    const float* b_ih1 = (const float*)d_in[6];
    const float* b_hh1 = (const float*)d_in[7];
    const float* Wt    = (const float*)d_in[8];
    const float* bt    = (const float*)d_in[9];
    const float* wk    = (const float*)d_in[10];
    const float* bk    = (const float*)d_in[11];
    const float* W1    = (const float*)d_in[12];
    const float* b1    = (const float*)d_in[13];
    const float* W2    = (const float*)d_in[14];
    const float* b2    = (const float*)d_in[15];
    const float* W_ih2 = (const float*)d_in[16];
    const float* W_hh2 = (const float*)d_in[17];
    const float* b_ih2 = (const float*)d_in[18];
    const float* b_hh2 = (const float*)d_in[19];
    const float* Wf1   = (const float*)d_in[20];
    const float* bf1   = (const float*)d_in[21];
    const float* Wf2   = (const float*)d_in[22];
    const float* bf2   = (const float*)d_in[23];
    float* out = (float*)d_out;

    // k_edge smem: 25664 floats + 528 ints = 104768 bytes
    const int edge_smem = 25664 * 4 + 528 * 4;
    cudaFuncSetAttribute(k_edge, cudaFuncAttributeMaxDynamicSharedMemorySize, edge_smem);

    k_lstm1<<<125, 128>>>(prices, W_ih1, W_hh1, b_ih1, b_hh1);
    dim3 ggrid((TN + 63) / 64, (GPW + 63) / 64);
    k_gemm_gp<<<ggrid, 256>>>(node_embs, W1, W_ih2);
    k_edge<<<TN, 256, edge_smem>>>(adj, mem, Wt, bt, wk, bk, W1, b1, W2, b2, W_ih2);
    k_lstm2<<<125, 128>>>(W_hh2, b_ih2, b_hh2, Wf1, bf1, Wf2, bf2, out);
}

// round 5
// speedup vs baseline: 1.5979x; 1.0831x over previous
#include <cuda_runtime.h>
#include <cstdint>

// ---------------------------------------------------------------------------
// StockModel: T=4, N=500, E=16, K=32, H=32, D=768, ZD=800, EH=200
//
//  K1  k_lstm1: prices (T,N,1) -> p_seq (T,N,32)            [warp/stock]
//  K2  k_mid:   blocks [0,500):  attn -> d_alpha[32000][32]
//               (thread = (row,e) x 8 i's, register softmax, no shuffles)
//               blocks [500,692): GEMM GP = node_embs @ [W1b|Wih2b]
//  K3  k_edge2: per (t,n): gather, vc, edge scores, att, hgX
//  K4  k_lstm2: hgX -> h_n -> out (N,2)                     [warp/stock]
// ---------------------------------------------------------------------------

#define TT 4
#define NS 500
#define EE 16
#define KK 32
#define HH 32
#define DD 768
#define ZDIM 800
#define GPW 328          // 200 (G) + 128 (P)
#define TN 2000          // T*N
#define NROWS (TN * EE)  // 32000 attn rows

__device__ float d_pseq[TN * HH];
__device__ float d_GP[TN * GPW];
__device__ float d_alpha[NROWS * KK];   // softmax-combined vertex weights
__device__ float d_hgX[TN * 128];

__device__ __forceinline__ float sigf(float x) { return 1.0f / (1.0f + __expf(-x)); }

// ===========================================================================
// K1: price LSTM, one warp per stock. Whh preloaded via smem transpose.
// ===========================================================================
__global__ __launch_bounds__(128) void k_lstm1(
    const float* __restrict__ prices,
    const float* __restrict__ Wih, const float* __restrict__ Whh,
    const float* __restrict__ bih, const float* __restrict__ bhh)
{
    __shared__ float whs[128 * 33];
    int tid = threadIdx.x;
    for (int idx = tid; idx < 4096; idx += 128)
        whs[(idx >> 5) * 33 + (idx & 31)] = Whh[idx];
    __syncthreads();

    int warp = (blockIdx.x * blockDim.x + tid) >> 5;
    int lane = tid & 31;
    if (warp >= NS) return;
    int n = warp;

    float wxi = Wih[lane],      wxf = Wih[32 + lane];
    float wxg = Wih[64 + lane], wxo = Wih[96 + lane];
    float bi = bih[lane]      + bhh[lane];
    float bf = bih[32 + lane] + bhh[32 + lane];
    float bg = bih[64 + lane] + bhh[64 + lane];
    float bo = bih[96 + lane] + bhh[96 + lane];

    float whi[32], whf[32], whg[32], who[32];
#pragma unroll
    for (int l = 0; l < 32; l++) {
        whi[l] = whs[lane * 33 + l];
        whf[l] = whs[(32 + lane) * 33 + l];
        whg[l] = whs[(64 + lane) * 33 + l];
        who[l] = whs[(96 + lane) * 33 + l];
    }

    float h = 0.0f, c = 0.0f;
#pragma unroll
    for (int t = 0; t < TT; t++) {
        float x = prices[t * NS + n];
        float zi = fmaf(wxi, x, bi), zf = fmaf(wxf, x, bf);
        float zg = fmaf(wxg, x, bg), zo = fmaf(wxo, x, bo);
#pragma unroll
        for (int l = 0; l < 32; l++) {
            float hl = __shfl_sync(0xffffffffu, h, l);
            zi = fmaf(whi[l], hl, zi);
            zf = fmaf(whf[l], hl, zf);
            zg = fmaf(whg[l], hl, zg);
            zo = fmaf(who[l], hl, zo);
        }
        c = sigf(zf) * c + sigf(zi) * tanhf(zg);
        h = sigf(zo) * tanhf(c);
        d_pseq[(t * NS + n) * HH + lane] = h;
    }
}

// ===========================================================================
// K2: fused attn + GEMM.
//   blocks [0,500): attn. 64 rows x 4 i-quarters. 8 steps of i.
//     thread owns row (tn,e), quarter q handles i = 8q+s at step s.
//     Full softmax row in registers -> acc[j] += wk[i]*exp(m_j)/sum.
//   blocks [500,692): GEMM GP = ne(2000x768) @ B(768x328), 64x64 tile.
// ===========================================================================
#define ATTN_BLOCKS 500
#define GEMM_RB 32
#define GEMM_CB 6
#define GEMM_BLOCKS (GEMM_RB * GEMM_CB)

__global__ __launch_bounds__(256) void k_mid(
    const int* __restrict__ adj, const int* __restrict__ mem,
    const float* __restrict__ Wt, const float* __restrict__ bt,
    const float* __restrict__ wk,
    const float* __restrict__ ne,
    const float* __restrict__ W1,
    const float* __restrict__ Wih2)
{
    extern __shared__ float dyn[];
    int tid = threadIdx.x;

    if (blockIdx.x < ATTN_BLOCKS) {
        // -------- attention part --------
        float* wt_s = dyn;            // [4][32][32] = 4096
        float* bt_s = dyn + 4096;     // [4][32]     = 128
        float* wk_s = dyn + 4224;     // [4]
        // red overlays dyn[0..8192) after the main loop

        int rloc = tid & 63, q = tid >> 6;
        int row  = blockIdx.x * 64 + rloc;    // < 32000 always
        int tn = row >> 4, e = row & 15;
        int tN = (tn / NS) * NS;
        int a  = adj[tn * EE + e];
        int membase = (tN + a) * KK;

        float acc[32];
#pragma unroll
        for (int j = 0; j < 32; j++) acc[j] = 0.0f;

        for (int s = 0; s < 8; s++) {
            // stage Wt rows for i = 8q+s (thread loads within its own quarter)
            {
                const float4* src = (const float4*)(Wt + (8 * q + s) * 1024 + rloc * 16);
                float4* dst = (float4*)(wt_s + q * 1024 + rloc * 16);
                dst[0] = src[0]; dst[1] = src[1]; dst[2] = src[2]; dst[3] = src[3];
                if (tid < 128) bt_s[(tid >> 5) * 32 + (tid & 31)] = bt[(8 * (tid >> 5) + s) * 32 + (tid & 31)];
                if (tid < 4)   wk_s[tid] = wk[8 * tid + s];
            }
            __syncthreads();

            int i = 8 * q + s;
            int midx = mem[membase + i];
            const float4* pr = (const float4*)(d_pseq + (tN + midx) * HH);
            float4 rr[8];
#pragma unroll
            for (int u = 0; u < 8; u++) rr[u] = pr[u];

            const float* wb = wt_s + q * 1024;
            float em[32];
            float srow = 0.0f;
#pragma unroll
            for (int j = 0; j < 32; j++) {
                const float4* w4 = (const float4*)(wb + j * 32);
                float m = bt_s[q * 32 + j];
#pragma unroll
                for (int u = 0; u < 8; u++) {
                    float4 w = w4[u];
                    m = fmaf(w.x, rr[u].x, m);
                    m = fmaf(w.y, rr[u].y, m);
                    m = fmaf(w.z, rr[u].z, m);
                    m = fmaf(w.w, rr[u].w, m);
                }
                float ev = __expf(m);   // |m| small: no max-subtraction needed
                em[j] = ev;
                srow += ev;
            }
            float f = __fdividef(wk_s[q], srow);
#pragma unroll
            for (int j = 0; j < 32; j++) acc[j] = fmaf(em[j], f, acc[j]);
            __syncthreads();
        }

        // cross-quarter reduction (red overlays wt_s region)
        float* red = dyn;   // [4][64][32] = 8192
        {
            float4* rp = (float4*)(red + q * 2048 + rloc * 32);
#pragma unroll
            for (int u = 0; u < 8; u++)
                rp[u] = make_float4(acc[u * 4], acc[u * 4 + 1], acc[u * 4 + 2], acc[u * 4 + 3]);
        }
        __syncthreads();
        for (int o = tid; o < 512; o += 256) {
            const float4* r0 = (const float4*)(red + o * 4);
            const float4* r1 = (const float4*)(red + 2048 + o * 4);
            const float4* r2 = (const float4*)(red + 4096 + o * 4);
            const float4* r3 = (const float4*)(red + 6144 + o * 4);
            float4 v0 = r0[0], v1 = r1[0], v2 = r2[0], v3 = r3[0];
            float4 v = make_float4(v0.x + v1.x + v2.x + v3.x,
                                   v0.y + v1.y + v2.y + v3.y,
                                   v0.z + v1.z + v2.z + v3.z,
                                   v0.w + v1.w + v2.w + v3.w);
            *(float4*)(d_alpha + blockIdx.x * 2048 + o * 4) = v;
        }
    } else {
        // -------- GEMM part --------
        float* As = dyn;          // [16][64]
        float* Bs = dyn + 1024;   // [16][64]
        int bx = blockIdx.x - ATTN_BLOCKS;
        int rb = (bx & 31) * 64, cb = (bx >> 5) * 64;
        int tx = tid & 15, ty = tid >> 4;
        int lm = tid >> 2;
        int lk = (tid & 3) * 4;

        float acc[4][4];
#pragma unroll
        for (int r = 0; r < 4; r++)
#pragma unroll
            for (int cq = 0; cq < 4; cq++) acc[r][cq] = 0.0f;

        int arow = rb + lm;
        int bcol = cb + lm;

        for (int k0 = 0; k0 < DD; k0 += 16) {
            float4 av = make_float4(0.f, 0.f, 0.f, 0.f);
            if (arow < TN) av = *(const float4*)(ne + arow * DD + k0 + lk);
            float4 bv = make_float4(0.f, 0.f, 0.f, 0.f);
            if (bcol < 200)      bv = *(const float4*)(W1 + bcol * ZDIM + 32 + k0 + lk);
            else if (bcol < GPW) bv = *(const float4*)(Wih2 + (bcol - 200) * ZDIM + 32 + k0 + lk);
            As[(lk + 0) * 64 + lm] = av.x; As[(lk + 1) * 64 + lm] = av.y;
            As[(lk + 2) * 64 + lm] = av.z; As[(lk + 3) * 64 + lm] = av.w;
            Bs[(lk + 0) * 64 + lm] = bv.x; Bs[(lk + 1) * 64 + lm] = bv.y;
            Bs[(lk + 2) * 64 + lm] = bv.z; Bs[(lk + 3) * 64 + lm] = bv.w;
            __syncthreads();
#pragma unroll
            for (int k = 0; k < 16; k++) {
                float4 a4 = *(const float4*)(&As[k * 64 + ty * 4]);
                float4 b4 = *(const float4*)(&Bs[k * 64 + tx * 4]);
                float ar[4] = {a4.x, a4.y, a4.z, a4.w};
                float br[4] = {b4.x, b4.y, b4.z, b4.w};
#pragma unroll
                for (int r = 0; r < 4; r++)
#pragma unroll
                    for (int cq = 0; cq < 4; cq++)
                        acc[r][cq] = fmaf(ar[r], br[cq], acc[r][cq]);
            }
            __syncthreads();
        }
#pragma unroll
        for (int r = 0; r < 4; r++) {
            int rrow = rb + ty * 4 + r;
            int col = cb + tx * 4;
            if (rrow < TN && col < GPW) {
                float4 v = make_float4(acc[r][0], acc[r][1], acc[r][2], acc[r][3]);
                *(float4*)(d_GP + rrow * GPW + col) = v;
            }
        }
    }
}

// ===========================================================================
// K3: per (t,n): gather region, vc, edge scores, edge softmax, hgX.
// ===========================================================================
__global__ __launch_bounds__(256) void k_edge2(
    const int* __restrict__ adj, const int* __restrict__ mem,
    const float* __restrict__ bk,
    const float* __restrict__ W1, const float* __restrict__ b1,
    const float* __restrict__ W2, const float* __restrict__ b2,
    const float* __restrict__ Wih2)
{
    extern __shared__ float sm[];
    float* region = sm;                  // [e][k][d] 16384
    float* wihAT  = region + 16384;      // [d][g]    4096
    float* alpha  = wihAT + 4096;        // [e][j]    512
    float* vc     = alpha + 512;         // [e][d]    512
    float* hgv_s  = vc + 512;            // 32
    float* svals  = hgv_s + 32;          // 16
    float* satt   = svals + 16;          // 16
    int*   sadj   = (int*)(satt + 16);   // 16
    int*   midx   = sadj + 16;           // 512

    int tid = threadIdx.x;
    int bid = blockIdx.x;
    int tN  = (bid / NS) * NS;

    if (tid < EE) sadj[tid] = adj[bid * EE + tid];
    // alpha rows are contiguous per block
    for (int q = tid; q < 512; q += 256) alpha[q] = d_alpha[bid * 512 + q];
    // stage Wih2[:, :32] transposed: wihAT[d*128+g]
    for (int idx = tid; idx < 4096; idx += 256) {
        int d = idx >> 7, g = idx & 127;
        wihAT[idx] = __ldg(Wih2 + g * ZDIM + d);
    }
    __syncthreads();

    for (int q = tid; q < EE * KK; q += 256)
        midx[q] = mem[(tN + sadj[q >> 5]) * KK + (q & 31)];
    __syncthreads();

    for (int q = tid; q < EE * KK * HH; q += 256)
        region[q] = d_pseq[(tN + midx[q >> 5]) * HH + (q & 31)];
    __syncthreads();

    // vc[e][d] = bk + sum_j alpha[e][j] * region[e][j][d]
    float bk0 = __ldg(bk);
    for (int q = tid; q < EE * KK; q += 256) {
        int e = q >> 5, d = q & 31;
        float acc = bk0;
#pragma unroll
        for (int j = 0; j < 32; j++)
            acc = fmaf(alpha[e * 32 + j], region[e * 1024 + j * 32 + d], acc);
        vc[q] = acc;
    }
    __syncthreads();

    // ---- edge scores: 16 threads/edge over m in [0,200) ----
    {
        int e = tid >> 4, q = tid & 15;
        const float* vce = vc + e * 32;
        const float* Grow = d_GP + (tN + sadj[e]) * GPW;
        float partial = 0.0f;
        for (int m = q; m < 200; m += 16) {
            float acc = __ldg(b1 + m) + Grow[m];
            const float4* w4 = (const float4*)(W1 + m * ZDIM);
#pragma unroll
            for (int dq = 0; dq < 8; dq++) {
                float4 v = w4[dq];
                acc = fmaf(v.x, vce[dq * 4],     acc);
                acc = fmaf(v.y, vce[dq * 4 + 1], acc);
                acc = fmaf(v.z, vce[dq * 4 + 2], acc);
                acc = fmaf(v.w, vce[dq * 4 + 3], acc);
            }
            partial = fmaf(__ldg(W2 + m), fmaxf(acc, 0.0f), partial);
        }
#pragma unroll
        for (int off = 8; off > 0; off >>= 1)
            partial += __shfl_xor_sync(0xffffffffu, partial, off);
        if (q == 0) svals[e] = partial + __ldg(b2);
    }
    __syncthreads();

    if (tid == 0) {
        float mx = svals[0];
#pragma unroll
        for (int e = 1; e < EE; e++) mx = fmaxf(mx, svals[e]);
        float s = 0.0f;
#pragma unroll
        for (int e = 0; e < EE; e++) { float v = __expf(svals[e] - mx); satt[e] = v; s += v; }
        float inv = 1.0f / s;
#pragma unroll
        for (int e = 0; e < EE; e++) satt[e] *= inv;
    }
    __syncthreads();

    if (tid < 32) {
        float acc = 0.0f;
#pragma unroll
        for (int e = 0; e < EE; e++) acc = fmaf(satt[e], vc[e * 32 + tid], acc);
        hgv_s[tid] = acc;
    }
    __syncthreads();

    // hgX[g] = sum_e att_e * P[t,a_e,g] + sum_d Wih2[g][d] * hgv[d]
    if (tid < 128) {
        int g = tid;
        float acc = 0.0f;
#pragma unroll
        for (int e = 0; e < EE; e++)
            acc = fmaf(satt[e], d_GP[(tN + sadj[e]) * GPW + 200 + g], acc);
#pragma unroll
        for (int d = 0; d < 32; d++)
            acc = fmaf(wihAT[d * 128 + g], hgv_s[d], acc);
        d_hgX[bid * 128 + g] = acc;
    }
}

// ===========================================================================
// K4: second LSTM + heads, one warp per stock. Whh preloaded via smem.
// ===========================================================================
__global__ __launch_bounds__(128) void k_lstm2(
    const float* __restrict__ Whh2,
    const float* __restrict__ bih2, const float* __restrict__ bhh2,
    const float* __restrict__ Wf1, const float* __restrict__ bf1,
    const float* __restrict__ Wf2, const float* __restrict__ bf2,
    float* __restrict__ out)
{
    __shared__ float whs[128 * 33];
    int tid = threadIdx.x;
    for (int idx = tid; idx < 4096; idx += 128)
        whs[(idx >> 5) * 33 + (idx & 31)] = Whh2[idx];
    __syncthreads();

    int warp = (blockIdx.x * blockDim.x + tid) >> 5;
    int lane = tid & 31;
    if (warp >= NS) return;
    int n = warp;

    float bi = bih2[lane]      + bhh2[lane];
    float bf = bih2[32 + lane] + bhh2[32 + lane];
    float bg = bih2[64 + lane] + bhh2[64 + lane];
    float bo = bih2[96 + lane] + bhh2[96 + lane];

    float whi[32], whf[32], whg[32], who[32];
#pragma unroll
    for (int l = 0; l < 32; l++) {
        whi[l] = whs[lane * 33 + l];
        whf[l] = whs[(32 + lane) * 33 + l];
        whg[l] = whs[(64 + lane) * 33 + l];
        who[l] = whs[(96 + lane) * 33 + l];
    }

    float h = 0.0f, c = 0.0f;
#pragma unroll
    for (int t = 0; t < TT; t++) {
        const float* hx = d_hgX + (t * NS + n) * 128;
        float zi = bi + hx[lane];
        float zf = bf + hx[32 + lane];
        float zg = bg + hx[64 + lane];
        float zo = bo + hx[96 + lane];
#pragma unroll
        for (int l = 0; l < 32; l++) {
            float hl = __shfl_sync(0xffffffffu, h, l);
            zi = fmaf(whi[l], hl, zi);
            zf = fmaf(whf[l], hl, zf);
            zg = fmaf(whg[l], hl, zg);
            zo = fmaf(who[l], hl, zo);
        }
        c = sigf(zf) * c + sigf(zi) * tanhf(zg);
        h = sigf(zo) * tanhf(c);
    }

    float f1a = bf1[lane], f1b = bf1[32 + lane];
#pragma unroll
    for (int l = 0; l < 32; l++) {
        float hl = __shfl_sync(0xffffffffu, h, l);
        f1a = fmaf(Wf1[lane * 32 + l], hl, f1a);
        f1b = fmaf(Wf1[(32 + lane) * 32 + l], hl, f1b);
    }
    float p0 = Wf2[lane] * f1a + Wf2[32 + lane] * f1b;
    float p1 = Wf2[64 + lane] * f1a + Wf2[96 + lane] * f1b;
#pragma unroll
    for (int off = 16; off > 0; off >>= 1) {
        p0 += __shfl_xor_sync(0xffffffffu, p0, off);
        p1 += __shfl_xor_sync(0xffffffffu, p1, off);
    }
    if (lane == 0) {
        out[n * 2]     = p0 + bf2[0];
        out[n * 2 + 1] = p1 + bf2[1];
    }
}

// ===========================================================================
extern "C" void kernel_launch(void* const* d_in, const int* in_sizes, int n_in,
                              void* d_out, int out_size)
{
    const float* prices    = (const float*)d_in[0];
    const float* node_embs = (const float*)d_in[1];
    const int*   adj       = (const int*)  d_in[2];
    const int*   mem       = (const int*)  d_in[3];
    const float* W_ih1 = (const float*)d_in[4];
    const float* W_hh1 = (const float*)d_in[5];
    const float* b_ih1 = (const float*)d_in[6];
    const float* b_hh1 = (const float*)d_in[7];
    const float* Wt    = (const float*)d_in[8];
    const float* bt    = (const float*)d_in[9];
    const float* wk    = (const float*)d_in[10];
    const float* bk    = (const float*)d_in[11];
    const float* W1    = (const float*)d_in[12];
    const float* b1    = (const float*)d_in[13];
    const float* W2    = (const float*)d_in[14];
    const float* b2    = (const float*)d_in[15];
    const float* W_ih2 = (const float*)d_in[16];
    const float* W_hh2 = (const float*)d_in[17];
    const float* b_ih2 = (const float*)d_in[18];
    const float* b_hh2 = (const float*)d_in[19];
    const float* Wf1   = (const float*)d_in[20];
    const float* bf1   = (const float*)d_in[21];
    const float* Wf2   = (const float*)d_in[22];
    const float* bf2   = (const float*)d_in[23];
    float* out = (float*)d_out;

    const int mid_smem  = 8192 * 4;                    // 32 KB (attn red / wt+gemm tiles)
    const int edge_smem = (16384 + 4096 + 512 + 512 + 32 + 16 + 16) * 4 + (16 + 512) * 4;
    cudaFuncSetAttribute(k_mid,   cudaFuncAttributeMaxDynamicSharedMemorySize, mid_smem);
    cudaFuncSetAttribute(k_edge2, cudaFuncAttributeMaxDynamicSharedMemorySize, edge_smem);

    k_lstm1<<<125, 128>>>(prices, W_ih1, W_hh1, b_ih1, b_hh1);
    k_mid<<<ATTN_BLOCKS + GEMM_BLOCKS, 256, mid_smem>>>(
        adj, mem, Wt, bt, wk, node_embs, W1, W_ih2);
    k_edge2<<<TN, 256, edge_smem>>>(adj, mem, bk, W1, b1, W2, b2, W_ih2);
    k_lstm2<<<125, 128>>>(W_hh2, b_ih2, b_hh2, Wf1, bf1, Wf2, bf2, out);
}

// round 8
// speedup vs baseline: 1.8986x; 1.1882x over previous
#include <cuda_runtime.h>
#include <cstdint>

// ---------------------------------------------------------------------------
// StockModel: T=4, N=500, E=16, K=32, H=32, D=768, ZD=800, EH=200
//
//  K1  k_lstm1: prices -> p_seq (T,N,32); block 125 transposes W1a -> d_w1aT
//  K2  k_gemm:  GP = node_embs(2000x768) @ [W1b|Wih2b](768x328)
//  K3  k_attn:  vertex-conv attention -> d_alpha[32000][32]
//               (register softmax, cooperative row staging, broadcast Wt LDS)
//  K4  k_edge2: per (t,n): gather, vc, edge scores (smem W1aT), att,
//               outputs d_hgv (32) + d_hgP (128)
//  K5  k_lstm2: gates = hgP + Wih2a@hgv (smem) -> h_n -> out (N,2)
// ---------------------------------------------------------------------------

#define TT 4
#define NS 500
#define EE 16
#define KK 32
#define HH 32
#define DD 768
#define ZDIM 800
#define GPW 328
#define TN 2000
#define NROWS (TN * EE)

__device__ float d_pseq[TN * HH];
__device__ float d_GP[TN * GPW];
__device__ float d_alpha[NROWS * KK];
__device__ float d_hgv[TN * HH];
__device__ float d_hgP[TN * 128];
__device__ float d_w1aT[32 * 200];     // W1[:, :32] transposed: [d][m]

__device__ __forceinline__ float sigf(float x) { return 1.0f / (1.0f + __expf(-x)); }

// ===========================================================================
// K1: price LSTM (blocks 0..124), W1a transpose (block 125).
// ===========================================================================
__global__ __launch_bounds__(128) void k_lstm1(
    const float* __restrict__ prices,
    const float* __restrict__ Wih, const float* __restrict__ Whh,
    const float* __restrict__ bih, const float* __restrict__ bhh,
    const float* __restrict__ W1)
{
    int tid = threadIdx.x;
    if (blockIdx.x == 125) {
        // d_w1aT[d][m] = W1[m][d], d<32, m<200. Read coalesced, write scattered.
        for (int idx = tid; idx < 6400; idx += 128) {
            int m = idx >> 5, d = idx & 31;
            d_w1aT[d * 200 + m] = W1[m * ZDIM + d];
        }
        return;
    }

    __shared__ float whs[128 * 33];
    for (int idx = tid; idx < 4096; idx += 128)
        whs[(idx >> 5) * 33 + (idx & 31)] = Whh[idx];
    __syncthreads();

    int warp = (blockIdx.x * blockDim.x + tid) >> 5;
    int lane = tid & 31;
    if (warp >= NS) return;
    int n = warp;

    float wxi = Wih[lane],      wxf = Wih[32 + lane];
    float wxg = Wih[64 + lane], wxo = Wih[96 + lane];
    float bi = bih[lane]      + bhh[lane];
    float bf = bih[32 + lane] + bhh[32 + lane];
    float bg = bih[64 + lane] + bhh[64 + lane];
    float bo = bih[96 + lane] + bhh[96 + lane];

    float whi[32], whf[32], whg[32], who[32];
#pragma unroll
    for (int l = 0; l < 32; l++) {
        whi[l] = whs[lane * 33 + l];
        whf[l] = whs[(32 + lane) * 33 + l];
        whg[l] = whs[(64 + lane) * 33 + l];
        who[l] = whs[(96 + lane) * 33 + l];
    }

    float h = 0.0f, c = 0.0f;
#pragma unroll
    for (int t = 0; t < TT; t++) {
        float x = prices[t * NS + n];
        float zi = fmaf(wxi, x, bi), zf = fmaf(wxf, x, bf);
        float zg = fmaf(wxg, x, bg), zo = fmaf(wxo, x, bo);
#pragma unroll
        for (int l = 0; l < 32; l++) {
            float hl = __shfl_sync(0xffffffffu, h, l);
            zi = fmaf(whi[l], hl, zi);
            zf = fmaf(whf[l], hl, zf);
            zg = fmaf(whg[l], hl, zg);
            zo = fmaf(who[l], hl, zo);
        }
        c = sigf(zf) * c + sigf(zi) * tanhf(zg);
        h = sigf(zo) * tanhf(c);
        d_pseq[(t * NS + n) * HH + lane] = h;
    }
}

// ===========================================================================
// K2: GP = node_embs (2000x768) @ B (768x328), 64x64 tile, BK=16, 4x4/thread
// ===========================================================================
__global__ __launch_bounds__(256) void k_gemm(
    const float* __restrict__ ne,
    const float* __restrict__ W1,
    const float* __restrict__ Wih2)
{
    __shared__ float As[16 * 64];
    __shared__ float Bs[16 * 64];
    int rb = blockIdx.x * 64, cb = blockIdx.y * 64;
    int tid = threadIdx.x;
    int tx = tid & 15, ty = tid >> 4;
    int lm = tid >> 2;
    int lk = (tid & 3) * 4;

    float acc[4][4];
#pragma unroll
    for (int r = 0; r < 4; r++)
#pragma unroll
        for (int cq = 0; cq < 4; cq++) acc[r][cq] = 0.0f;

    int arow = rb + lm;
    int bcol = cb + lm;

    for (int k0 = 0; k0 < DD; k0 += 16) {
        float4 av = make_float4(0.f, 0.f, 0.f, 0.f);
        if (arow < TN) av = *(const float4*)(ne + arow * DD + k0 + lk);
        float4 bv = make_float4(0.f, 0.f, 0.f, 0.f);
        if (bcol < 200)      bv = *(const float4*)(W1 + bcol * ZDIM + 32 + k0 + lk);
        else if (bcol < GPW) bv = *(const float4*)(Wih2 + (bcol - 200) * ZDIM + 32 + k0 + lk);
        As[(lk + 0) * 64 + lm] = av.x; As[(lk + 1) * 64 + lm] = av.y;
        As[(lk + 2) * 64 + lm] = av.z; As[(lk + 3) * 64 + lm] = av.w;
        Bs[(lk + 0) * 64 + lm] = bv.x; Bs[(lk + 1) * 64 + lm] = bv.y;
        Bs[(lk + 2) * 64 + lm] = bv.z; Bs[(lk + 3) * 64 + lm] = bv.w;
        __syncthreads();
#pragma unroll
        for (int k = 0; k < 16; k++) {
            float4 a4 = *(const float4*)(&As[k * 64 + ty * 4]);
            float4 b4 = *(const float4*)(&Bs[k * 64 + tx * 4]);
            float ar[4] = {a4.x, a4.y, a4.z, a4.w};
            float br[4] = {b4.x, b4.y, b4.z, b4.w};
#pragma unroll
            for (int r = 0; r < 4; r++)
#pragma unroll
                for (int cq = 0; cq < 4; cq++)
                    acc[r][cq] = fmaf(ar[r], br[cq], acc[r][cq]);
        }
        __syncthreads();
    }
#pragma unroll
    for (int r = 0; r < 4; r++) {
        int rrow = rb + ty * 4 + r;
        int col = cb + tx * 4;
        if (rrow < TN && col < GPW) {
            float4 v = make_float4(acc[r][0], acc[r][1], acc[r][2], acc[r][3]);
            *(float4*)(d_GP + rrow * GPW + col) = v;
        }
    }
}

// ===========================================================================
// K3: vertex-conv attention. 500 blocks x 256 threads.
// Thread = (row rloc 0..63, quarter q 0..3); 8 steps of i = 8q+s.
// Member rows cooperatively staged per step (coalesced LDG, stride-33 smem).
// ===========================================================================
#define AT_WTS   0        // 4096  wt_s[q][j][d]
#define AT_BTS   4096     // 128
#define AT_WKS   4224     // 16 (padded)
#define AT_MIDX  4240     // 2048 ints
#define AT_ADJ   6288     // 64 ints
#define AT_TNB   6352     // 64 ints
#define AT_ROWS  6416     // 256*33 = 8448 (reused as red[8192] at end)
#define AT_TOTAL 14864    // floats

__global__ __launch_bounds__(256) void k_attn(
    const int* __restrict__ adj, const int* __restrict__ mem,
    const float* __restrict__ Wt, const float* __restrict__ bt,
    const float* __restrict__ wk)
{
    extern __shared__ float dyn[];
    float* wt_s  = dyn + AT_WTS;
    float* bt_s  = dyn + AT_BTS;
    float* wk_s  = dyn + AT_WKS;
    int*   smidx = (int*)(dyn + AT_MIDX);
    int*   sadj  = (int*)(dyn + AT_ADJ);
    int*   stN   = (int*)(dyn + AT_TNB);
    float* srows = dyn + AT_ROWS;

    int tid = threadIdx.x;
    int rloc = tid & 63, q = tid >> 6;
    int w = tid >> 5, lane = tid & 31;

    if (tid < 64) {
        int row = blockIdx.x * 64 + tid;
        int tn = row >> 4, e = row & 15;
        sadj[tid] = adj[tn * EE + e];
        stN[tid]  = (tn / NS) * NS;
    }
    __syncthreads();
    for (int idx = tid; idx < 2048; idx += 256) {
        int r = idx >> 5, i = idx & 31;
        smidx[idx] = stN[r] + mem[(stN[r] + sadj[r]) * KK + i];
    }

    float acc[32];
#pragma unroll
    for (int j = 0; j < 32; j++) acc[j] = 0.0f;

    for (int s = 0; s < 8; s++) {
        __syncthreads();   // protect srows/wt_s from previous step's readers
        // stage Wt[i=8q+s], bt, wk
        {
            const float4* src = (const float4*)(Wt + (8 * q + s) * 1024 + rloc * 16);
            float4* dst = (float4*)(wt_s + q * 1024 + rloc * 16);
            dst[0] = src[0]; dst[1] = src[1]; dst[2] = src[2]; dst[3] = src[3];
            if (tid < 128) bt_s[(tid >> 5) * 32 + lane] = bt[(8 * (tid >> 5) + s) * 32 + lane];
            if (tid < 4)   wk_s[tid] = wk[8 * tid + s];
        }
        // stage member rows: warp w stages rows w*32 .. w*32+31 (coalesced)
        for (int r2 = 0; r2 < 32; r2++) {
            int r = w * 32 + r2;
            int rl = r & 63, qq = r >> 6;
            int mrow = smidx[rl * 32 + 8 * qq + s];
            srows[r * 33 + lane] = d_pseq[mrow * 32 + lane];
        }
        __syncthreads();

        // consume: full softmax row in registers
        float rg[32];
        {
            const float* base = srows + (q * 64 + rloc) * 33;
#pragma unroll
            for (int d = 0; d < 32; d++) rg[d] = base[d];
        }
        const float* wb = wt_s + q * 1024;
        float em[32];
        float srow = 0.0f;
#pragma unroll
        for (int j = 0; j < 32; j++) {
            const float4* w4 = (const float4*)(wb + j * 32);
            float m = bt_s[q * 32 + j];
#pragma unroll
            for (int u = 0; u < 8; u++) {
                float4 wv = w4[u];
                m = fmaf(wv.x, rg[u * 4],     m);
                m = fmaf(wv.y, rg[u * 4 + 1], m);
                m = fmaf(wv.z, rg[u * 4 + 2], m);
                m = fmaf(wv.w, rg[u * 4 + 3], m);
            }
            float ev = __expf(m);   // |m| small: no max-subtraction needed
            em[j] = ev;
            srow += ev;
        }
        float f = __fdividef(wk_s[q], srow);
#pragma unroll
        for (int j = 0; j < 32; j++) acc[j] = fmaf(em[j], f, acc[j]);
    }

    // cross-quarter reduction (red overlays srows)
    __syncthreads();
    float* red = dyn + AT_ROWS;
    {
        float4* rp = (float4*)(red + q * 2048 + rloc * 32);
#pragma unroll
        for (int u = 0; u < 8; u++)
            rp[u] = make_float4(acc[u * 4], acc[u * 4 + 1], acc[u * 4 + 2], acc[u * 4 + 3]);
    }
    __syncthreads();
    for (int o = tid; o < 512; o += 256) {
        const float4 v0 = *(const float4*)(red + o * 4);
        const float4 v1 = *(const float4*)(red + 2048 + o * 4);
        const float4 v2 = *(const float4*)(red + 4096 + o * 4);
        const float4 v3 = *(const float4*)(red + 6144 + o * 4);
        float4 v = make_float4(v0.x + v1.x + v2.x + v3.x,
                               v0.y + v1.y + v2.y + v3.y,
                               v0.z + v1.z + v2.z + v3.z,
                               v0.w + v1.w + v2.w + v3.w);
        *(float4*)(d_alpha + blockIdx.x * 2048 + o * 4) = v;
    }
}

// ===========================================================================
// K4: per (t,n): gather, vc, edge scores (smem W1aT, vc in regs), att,
//     outputs d_hgv + d_hgP. 2000 blocks x 256 threads. smem 99.2KB -> 2/SM.
// ===========================================================================
#define E_REGION 0         // 16384
#define E_W1AT   16384     // 6400  [d][m]
#define E_B1S    22784     // 200
#define E_W2S    22984     // 200
#define E_ALPHA  23184     // 512
#define E_VC     23696     // 512
#define E_HGV    24208     // 32
#define E_SVALS  24240     // 16
#define E_SATT   24256     // 16
#define E_SADJ   24272     // 16 ints
#define E_MIDX   24288     // 512 ints
#define E_TOTAL  24800     // floats

__global__ __launch_bounds__(256) void k_edge2(
    const int* __restrict__ adj, const int* __restrict__ mem,
    const float* __restrict__ bk,
    const float* __restrict__ b1,
    const float* __restrict__ W2, const float* __restrict__ b2)
{
    extern __shared__ float sm[];
    float* region = sm + E_REGION;
    float* w1aT   = sm + E_W1AT;
    float* b1s    = sm + E_B1S;
    float* w2s    = sm + E_W2S;
    float* alpha  = sm + E_ALPHA;
    float* vc     = sm + E_VC;
    float* svals  = sm + E_SVALS;
    float* satt   = sm + E_SATT;
    int*   sadj   = (int*)(sm + E_SADJ);
    int*   midx   = (int*)(sm + E_MIDX);

    int tid = threadIdx.x;
    int bid = blockIdx.x;
    int tN  = (bid / NS) * NS;

    if (tid < EE) sadj[tid] = adj[bid * EE + tid];
    for (int q = tid; q < 512; q += 256) alpha[q] = d_alpha[bid * 512 + q];
    for (int idx = tid; idx < 6400; idx += 256) w1aT[idx] = d_w1aT[idx];
    if (tid < 200) { b1s[tid] = b1[tid]; w2s[tid] = W2[tid]; }
    __syncthreads();

    for (int q = tid; q < EE * KK; q += 256)
        midx[q] = mem[(tN + sadj[q >> 5]) * KK + (q & 31)];
    __syncthreads();

    for (int q = tid; q < EE * KK * HH; q += 256)
        region[q] = d_pseq[(tN + midx[q >> 5]) * HH + (q & 31)];
    __syncthreads();

    // vc[e][d] = bk + sum_j alpha[e][j] * region[e][j][d]
    float bk0 = __ldg(bk);
    for (int q = tid; q < EE * KK; q += 256) {
        int e = q >> 5, d = q & 31;
        float acc = bk0;
#pragma unroll
        for (int j = 0; j < 32; j++)
            acc = fmaf(alpha[e * 32 + j], region[e * 1024 + j * 32 + d], acc);
        vc[q] = acc;
    }
    __syncthreads();

    // ---- edge scores: 16 threads/edge; W1a from smem, vc in registers ----
    {
        int e = tid >> 4, q = tid & 15;
        float vce[32];
#pragma unroll
        for (int d = 0; d < 32; d++) vce[d] = vc[e * 32 + d];
        const float* Grow = d_GP + (tN + sadj[e]) * GPW;
        float partial = 0.0f;
        for (int m = q; m < 200; m += 16) {
            float acc = b1s[m] + Grow[m];
#pragma unroll
            for (int d = 0; d < 32; d++)
                acc = fmaf(vce[d], w1aT[d * 200 + m], acc);
            partial = fmaf(w2s[m], fmaxf(acc, 0.0f), partial);
        }
#pragma unroll
        for (int off = 8; off > 0; off >>= 1)
            partial += __shfl_xor_sync(0xffffffffu, partial, off);
        if (q == 0) svals[e] = partial + __ldg(b2);
    }
    __syncthreads();

    if (tid == 0) {
        float mx = svals[0];
#pragma unroll
        for (int e = 1; e < EE; e++) mx = fmaxf(mx, svals[e]);
        float s = 0.0f;
#pragma unroll
        for (int e = 0; e < EE; e++) { float v = __expf(svals[e] - mx); satt[e] = v; s += v; }
        float inv = 1.0f / s;
#pragma unroll
        for (int e = 0; e < EE; e++) satt[e] *= inv;
    }
    __syncthreads();

    if (tid < 32) {
        float acc = 0.0f;
#pragma unroll
        for (int e = 0; e < EE; e++) acc = fmaf(satt[e], vc[e * 32 + tid], acc);
        d_hgv[bid * HH + tid] = acc;
    }
    if (tid < 128) {
        float acc = 0.0f;
#pragma unroll
        for (int e = 0; e < EE; e++)
            acc = fmaf(satt[e], d_GP[(tN + sadj[e]) * GPW + 200 + tid], acc);
        d_hgP[bid * 128 + tid] = acc;
    }
}

// ===========================================================================
// K5: second LSTM + heads. Gates = hgP + Wih2a @ hgv (smem-staged) + Whh2 h.
// ===========================================================================
__global__ __launch_bounds__(128) void k_lstm2(
    const float* __restrict__ Wih2, const float* __restrict__ Whh2,
    const float* __restrict__ bih2, const float* __restrict__ bhh2,
    const float* __restrict__ Wf1, const float* __restrict__ bf1,
    const float* __restrict__ Wf2, const float* __restrict__ bf2,
    float* __restrict__ out)
{
    __shared__ float whs[128 * 33];
    __shared__ float wia[128 * 33];   // Wih2[:, :32], [g][l] stride 33
    int tid = threadIdx.x;
    for (int idx = tid; idx < 4096; idx += 128) {
        int g = idx >> 5, l = idx & 31;
        whs[g * 33 + l] = Whh2[idx];
        wia[g * 33 + l] = Wih2[g * ZDIM + l];
    }
    __syncthreads();

    int warp = (blockIdx.x * blockDim.x + tid) >> 5;
    int lane = tid & 31;
    if (warp >= NS) return;
    int n = warp;

    float bi = bih2[lane]      + bhh2[lane];
    float bf = bih2[32 + lane] + bhh2[32 + lane];
    float bg = bih2[64 + lane] + bhh2[64 + lane];
    float bo = bih2[96 + lane] + bhh2[96 + lane];

    float whi[32], whf[32], whg[32], who[32];
#pragma unroll
    for (int l = 0; l < 32; l++) {
        whi[l] = whs[lane * 33 + l];
        whf[l] = whs[(32 + lane) * 33 + l];
        whg[l] = whs[(64 + lane) * 33 + l];
        who[l] = whs[(96 + lane) * 33 + l];
    }

    float h = 0.0f, c = 0.0f;
#pragma unroll
    for (int t = 0; t < TT; t++) {
        int row = t * NS + n;
        const float* hp = d_hgP + row * 128;
        float hvv = d_hgv[row * HH + lane];
        float zi = bi + hp[lane];
        float zf = bf + hp[32 + lane];
        float zg = bg + hp[64 + lane];
        float zo = bo + hp[96 + lane];
#pragma unroll
        for (int l = 0; l < 32; l++) {
            float hl  = __shfl_sync(0xffffffffu, h,   l);
            float hvl = __shfl_sync(0xffffffffu, hvv, l);
            zi = fmaf(whi[l], hl, zi);
            zf = fmaf(whf[l], hl, zf);
            zg = fmaf(whg[l], hl, zg);
            zo = fmaf(who[l], hl, zo);
            zi = fmaf(wia[lane * 33 + l],        hvl, zi);
            zf = fmaf(wia[(32 + lane) * 33 + l], hvl, zf);
            zg = fmaf(wia[(64 + lane) * 33 + l], hvl, zg);
            zo = fmaf(wia[(96 + lane) * 33 + l], hvl, zo);
        }
        c = sigf(zf) * c + sigf(zi) * tanhf(zg);
        h = sigf(zo) * tanhf(c);
    }

    float f1a = bf1[lane], f1b = bf1[32 + lane];
#pragma unroll
    for (int l = 0; l < 32; l++) {
        float hl = __shfl_sync(0xffffffffu, h, l);
        f1a = fmaf(Wf1[lane * 32 + l], hl, f1a);
        f1b = fmaf(Wf1[(32 + lane) * 32 + l], hl, f1b);
    }
    float p0 = Wf2[lane] * f1a + Wf2[32 + lane] * f1b;
    float p1 = Wf2[64 + lane] * f1a + Wf2[96 + lane] * f1b;
#pragma unroll
    for (int off = 16; off > 0; off >>= 1) {
        p0 += __shfl_xor_sync(0xffffffffu, p0, off);
        p1 += __shfl_xor_sync(0xffffffffu, p1, off);
    }
    if (lane == 0) {
        out[n * 2]     = p0 + bf2[0];
        out[n * 2 + 1] = p1 + bf2[1];
    }
}

// ===========================================================================
extern "C" void kernel_launch(void* const* d_in, const int* in_sizes, int n_in,
                              void* d_out, int out_size)
{
    const float* prices    = (const float*)d_in[0];
    const float* node_embs = (const float*)d_in[1];
    const int*   adj       = (const int*)  d_in[2];
    const int*   mem       = (const int*)  d_in[3];
    const float* W_ih1 = (const float*)d_in[4];
    const float* W_hh1 = (const float*)d_in[5];
    const float* b_ih1 = (const float*)d_in[6];
    const float* b_hh1 = (const float*)d_in[7];
    const float* Wt    = (const float*)d_in[8];
    const float* bt    = (const float*)d_in[9];
    const float* wk    = (const float*)d_in[10];
    const float* bk    = (const float*)d_in[11];
    const float* W1    = (const float*)d_in[12];
    const float* b1    = (const float*)d_in[13];
    const float* W2    = (const float*)d_in[14];
    const float* b2    = (const float*)d_in[15];
    const float* W_ih2 = (const float*)d_in[16];
    const float* W_hh2 = (const float*)d_in[17];
    const float* b_ih2 = (const float*)d_in[18];
    const float* b_hh2 = (const float*)d_in[19];
    const float* Wf1   = (const float*)d_in[20];
    const float* bf1   = (const float*)d_in[21];
    const float* Wf2   = (const float*)d_in[22];
    const float* bf2   = (const float*)d_in[23];
    float* out = (float*)d_out;

    const int attn_smem = AT_TOTAL * 4;   // 59456 B
    const int edge_smem = E_TOTAL * 4;    // 99200 B
    cudaFuncSetAttribute(k_attn,  cudaFuncAttributeMaxDynamicSharedMemorySize, attn_smem);
    cudaFuncSetAttribute(k_edge2, cudaFuncAttributeMaxDynamicSharedMemorySize, edge_smem);

    k_lstm1<<<126, 128>>>(prices, W_ih1, W_hh1, b_ih1, b_hh1, W1);
    dim3 ggrid((TN + 63) / 64, (GPW + 63) / 64);
    k_gemm<<<ggrid, 256>>>(node_embs, W1, W_ih2);
    k_attn<<<NROWS / 64, 256, attn_smem>>>(adj, mem, Wt, bt, wk);
    k_edge2<<<TN, 256, edge_smem>>>(adj, mem, bk, b1, W2, b2);
    k_lstm2<<<125, 128>>>(W_ih2, W_hh2, b_ih2, b_hh2, Wf1, bf1, Wf2, bf2, out);
}

// round 10
// speedup vs baseline: 2.2793x; 1.2005x over previous
#include <cuda_runtime.h>
#include <cstdint>

// ---------------------------------------------------------------------------
// StockModel: T=4, N=500, E=16, K=32, H=32, D=768, ZD=800, EH=200
//
//  K1  k_lstm1: prices -> p_seq (T,N,32); block 125 packs W1a -> d_w1p
//  K2  k_gemm:  GP = node_embs(2000x768) @ [W1b|Wih2b](768x328)
//  K3  k_attn:  vertex-conv attention -> d_alpha[32000][32]  (f32x2 FFMA2)
//  K4  k_edge2: per (t,n): fused gather+vc (no region smem), scores (f32x2),
//               att, outputs d_hgv + d_hgP.  smem 33.5KB -> 4 blocks/SM
//  K5  k_lstm2: gates = hgP + Wih2a@hgv (smem) -> h_n -> out (N,2)
// ---------------------------------------------------------------------------

#define TT 4
#define NS 500
#define EE 16
#define KK 32
#define HH 32
#define DD 768
#define ZDIM 800
#define GPW 328
#define TN 2000
#define NROWS (TN * EE)

__device__ float d_pseq[TN * HH];
__device__ float d_GP[TN * GPW];
__device__ float d_alpha[NROWS * KK];
__device__ float d_hgv[TN * HH];
__device__ float d_hgP[TN * 128];
__device__ float d_w1p[32 * 200];   // W1[:, :32] pair-packed: [(d2*200+m)*2+c] = W1[m][2*d2+c]

__device__ __forceinline__ float sigf(float x) { return 1.0f / (1.0f + __expf(-x)); }

// ---- packed f32x2 helpers (sm_100+) ----
__device__ __forceinline__ uint64_t pk2(float lo, float hi) {
    uint64_t r; asm("mov.b64 %0, {%1, %2};" : "=l"(r) : "f"(lo), "f"(hi)); return r;
}
__device__ __forceinline__ void ffma2(uint64_t& d, uint64_t a, uint64_t b) {
    asm("fma.rn.f32x2 %0, %1, %2, %3;" : "=l"(d) : "l"(a), "l"(b), "l"(d));
}
__device__ __forceinline__ float hadd2(uint64_t v) {
    float lo, hi; asm("mov.b64 {%0, %1}, %2;" : "=f"(lo), "=f"(hi) : "l"(v));
    return lo + hi;
}

// ===========================================================================
// K1: price LSTM (blocks 0..124), W1a pair-pack (block 125).
// ===========================================================================
__global__ __launch_bounds__(128) void k_lstm1(
    const float* __restrict__ prices,
    const float* __restrict__ Wih, const float* __restrict__ Whh,
    const float* __restrict__ bih, const float* __restrict__ bhh,
    const float* __restrict__ W1)
{
    int tid = threadIdx.x;
    if (blockIdx.x == 125) {
        for (int idx = tid; idx < 6400; idx += 128) {
            int pairIdx = idx >> 1, c = idx & 1;
            int d2 = pairIdx / 200, m = pairIdx % 200;
            d_w1p[idx] = W1[m * ZDIM + 2 * d2 + c];
        }
        return;
    }

    __shared__ float whs[128 * 33];
    for (int idx = tid; idx < 4096; idx += 128)
        whs[(idx >> 5) * 33 + (idx & 31)] = Whh[idx];
    __syncthreads();

    int warp = (blockIdx.x * blockDim.x + tid) >> 5;
    int lane = tid & 31;
    if (warp >= NS) return;
    int n = warp;

    float wxi = Wih[lane],      wxf = Wih[32 + lane];
    float wxg = Wih[64 + lane], wxo = Wih[96 + lane];
    float bi = bih[lane]      + bhh[lane];
    float bf = bih[32 + lane] + bhh[32 + lane];
    float bg = bih[64 + lane] + bhh[64 + lane];
    float bo = bih[96 + lane] + bhh[96 + lane];

    float whi[32], whf[32], whg[32], who[32];
#pragma unroll
    for (int l = 0; l < 32; l++) {
        whi[l] = whs[lane * 33 + l];
        whf[l] = whs[(32 + lane) * 33 + l];
        whg[l] = whs[(64 + lane) * 33 + l];
        who[l] = whs[(96 + lane) * 33 + l];
    }

    float h = 0.0f, c = 0.0f;
#pragma unroll
    for (int t = 0; t < TT; t++) {
        float x = prices[t * NS + n];
        float zi = fmaf(wxi, x, bi), zf = fmaf(wxf, x, bf);
        float zg = fmaf(wxg, x, bg), zo = fmaf(wxo, x, bo);
#pragma unroll
        for (int l = 0; l < 32; l++) {
            float hl = __shfl_sync(0xffffffffu, h, l);
            zi = fmaf(whi[l], hl, zi);
            zf = fmaf(whf[l], hl, zf);
            zg = fmaf(whg[l], hl, zg);
            zo = fmaf(who[l], hl, zo);
        }
        c = sigf(zf) * c + sigf(zi) * tanhf(zg);
        h = sigf(zo) * tanhf(c);
        d_pseq[(t * NS + n) * HH + lane] = h;
    }
}

// ===========================================================================
// K2: GP = node_embs (2000x768) @ B (768x328), 64x64 tile, BK=16, 4x4/thread
// ===========================================================================
__global__ __launch_bounds__(256) void k_gemm(
    const float* __restrict__ ne,
    const float* __restrict__ W1,
    const float* __restrict__ Wih2)
{
    __shared__ float As[16 * 64];
    __shared__ float Bs[16 * 64];
    int rb = blockIdx.x * 64, cb = blockIdx.y * 64;
    int tid = threadIdx.x;
    int tx = tid & 15, ty = tid >> 4;
    int lm = tid >> 2;
    int lk = (tid & 3) * 4;

    float acc[4][4];
#pragma unroll
    for (int r = 0; r < 4; r++)
#pragma unroll
        for (int cq = 0; cq < 4; cq++) acc[r][cq] = 0.0f;

    int arow = rb + lm;
    int bcol = cb + lm;

    for (int k0 = 0; k0 < DD; k0 += 16) {
        float4 av = make_float4(0.f, 0.f, 0.f, 0.f);
        if (arow < TN) av = *(const float4*)(ne + arow * DD + k0 + lk);
        float4 bv = make_float4(0.f, 0.f, 0.f, 0.f);
        if (bcol < 200)      bv = *(const float4*)(W1 + bcol * ZDIM + 32 + k0 + lk);
        else if (bcol < GPW) bv = *(const float4*)(Wih2 + (bcol - 200) * ZDIM + 32 + k0 + lk);
        As[(lk + 0) * 64 + lm] = av.x; As[(lk + 1) * 64 + lm] = av.y;
        As[(lk + 2) * 64 + lm] = av.z; As[(lk + 3) * 64 + lm] = av.w;
        Bs[(lk + 0) * 64 + lm] = bv.x; Bs[(lk + 1) * 64 + lm] = bv.y;
        Bs[(lk + 2) * 64 + lm] = bv.z; Bs[(lk + 3) * 64 + lm] = bv.w;
        __syncthreads();
#pragma unroll
        for (int k = 0; k < 16; k++) {
            float4 a4 = *(const float4*)(&As[k * 64 + ty * 4]);
            float4 b4 = *(const float4*)(&Bs[k * 64 + tx * 4]);
            float ar[4] = {a4.x, a4.y, a4.z, a4.w};
            float br[4] = {b4.x, b4.y, b4.z, b4.w};
#pragma unroll
            for (int r = 0; r < 4; r++)
#pragma unroll
                for (int cq = 0; cq < 4; cq++)
                    acc[r][cq] = fmaf(ar[r], br[cq], acc[r][cq]);
        }
        __syncthreads();
    }
#pragma unroll
    for (int r = 0; r < 4; r++) {
        int rrow = rb + ty * 4 + r;
        int col = cb + tx * 4;
        if (rrow < TN && col < GPW) {
            float4 v = make_float4(acc[r][0], acc[r][1], acc[r][2], acc[r][3]);
            *(float4*)(d_GP + rrow * GPW + col) = v;
        }
    }
}

// ===========================================================================
// K3: vertex-conv attention. 500 blocks x 256 threads. FFMA2 inner product.
// ===========================================================================
#define AT_WTS   0        // 4096  wt_s[q][j][d]
#define AT_BTS   4096     // 128
#define AT_WKS   4224     // 16 (padded)
#define AT_MIDX  4240     // 2048 ints
#define AT_ADJ   6288     // 64 ints
#define AT_TNB   6352     // 64 ints
#define AT_ROWS  6416     // 256*33 = 8448 (reused as red[8192] at end)
#define AT_TOTAL 14864    // floats

__global__ __launch_bounds__(256) void k_attn(
    const int* __restrict__ adj, const int* __restrict__ mem,
    const float* __restrict__ Wt, const float* __restrict__ bt,
    const float* __restrict__ wk)
{
    extern __shared__ float dyn[];
    float* wt_s  = dyn + AT_WTS;
    float* bt_s  = dyn + AT_BTS;
    float* wk_s  = dyn + AT_WKS;
    int*   smidx = (int*)(dyn + AT_MIDX);
    int*   sadj  = (int*)(dyn + AT_ADJ);
    int*   stN   = (int*)(dyn + AT_TNB);
    float* srows = dyn + AT_ROWS;

    int tid = threadIdx.x;
    int rloc = tid & 63, q = tid >> 6;
    int w = tid >> 5, lane = tid & 31;

    if (tid < 64) {
        int row = blockIdx.x * 64 + tid;
        int tn = row >> 4, e = row & 15;
        sadj[tid] = adj[tn * EE + e];
        stN[tid]  = (tn / NS) * NS;
    }
    __syncthreads();
    for (int idx = tid; idx < 2048; idx += 256) {
        int r = idx >> 5, i = idx & 31;
        smidx[idx] = stN[r] + mem[(stN[r] + sadj[r]) * KK + i];
    }

    float acc[32];
#pragma unroll
    for (int j = 0; j < 32; j++) acc[j] = 0.0f;

    for (int s = 0; s < 8; s++) {
        __syncthreads();   // protect srows/wt_s from previous step's readers
        // stage Wt[i=8q+s], bt, wk
        {
            const float4* src = (const float4*)(Wt + (8 * q + s) * 1024 + rloc * 16);
            float4* dst = (float4*)(wt_s + q * 1024 + rloc * 16);
            dst[0] = src[0]; dst[1] = src[1]; dst[2] = src[2]; dst[3] = src[3];
            if (tid < 128) bt_s[(tid >> 5) * 32 + lane] = bt[(8 * (tid >> 5) + s) * 32 + lane];
            if (tid < 4)   wk_s[tid] = wk[8 * tid + s];
        }
        // stage member rows: warp w stages rows w*32 .. w*32+31 (coalesced)
        for (int r2 = 0; r2 < 32; r2++) {
            int r = w * 32 + r2;
            int rl = r & 63, qq = r >> 6;
            int mrow = smidx[rl * 32 + 8 * qq + s];
            srows[r * 33 + lane] = d_pseq[mrow * 32 + lane];
        }
        __syncthreads();

        // consume: full softmax row in registers; packed f32x2 dot products
        uint64_t rgp[16];
        {
            const float* base = srows + (q * 64 + rloc) * 33;
#pragma unroll
            for (int d2 = 0; d2 < 16; d2++)
                rgp[d2] = pk2(base[2 * d2], base[2 * d2 + 1]);
        }
        const float* wb = wt_s + q * 1024;
        float em[32];
        float srow = 0.0f;
#pragma unroll
        for (int j = 0; j < 32; j++) {
            const ulonglong2* w2p = (const ulonglong2*)(wb + j * 32);
            uint64_t mac = pk2(bt_s[q * 32 + j], 0.0f);
#pragma unroll
            for (int u = 0; u < 8; u++) {
                ulonglong2 wv = w2p[u];
                ffma2(mac, wv.x, rgp[2 * u]);
                ffma2(mac, wv.y, rgp[2 * u + 1]);
            }
            float ev = __expf(hadd2(mac));   // |m| small: no max-subtraction needed
            em[j] = ev;
            srow += ev;
        }
        float f = __fdividef(wk_s[q], srow);
#pragma unroll
        for (int j = 0; j < 32; j++) acc[j] = fmaf(em[j], f, acc[j]);
    }

    // cross-quarter reduction (red overlays srows)
    __syncthreads();
    float* red = dyn + AT_ROWS;
    {
        float4* rp = (float4*)(red + q * 2048 + rloc * 32);
#pragma unroll
        for (int u = 0; u < 8; u++)
            rp[u] = make_float4(acc[u * 4], acc[u * 4 + 1], acc[u * 4 + 2], acc[u * 4 + 3]);
    }
    __syncthreads();
    for (int o = tid; o < 512; o += 256) {
        const float4 v0 = *(const float4*)(red + o * 4);
        const float4 v1 = *(const float4*)(red + 2048 + o * 4);
        const float4 v2 = *(const float4*)(red + 4096 + o * 4);
        const float4 v3 = *(const float4*)(red + 6144 + o * 4);
        float4 v = make_float4(v0.x + v1.x + v2.x + v3.x,
                               v0.y + v1.y + v2.y + v3.y,
                               v0.z + v1.z + v2.z + v3.z,
                               v0.w + v1.w + v2.w + v3.w);
        *(float4*)(d_alpha + blockIdx.x * 2048 + o * 4) = v;
    }
}

// ===========================================================================
// K4: per (t,n): fused gather+vc (no region smem), scores (f32x2), att,
//     outputs d_hgv + d_hgP. 2000 blocks x 256 threads. smem 33.5KB.
// ===========================================================================
#define E_W1P    0         // 6400 (pair-packed, 8B-aligned at 0)
#define E_ALPHA  6400      // 512
#define E_VC     6912      // 512
#define E_B1S    7424      // 200
#define E_W2S    7624      // 200
#define E_SVALS  7824      // 16
#define E_SATT   7840      // 16
#define E_SADJ   7856      // 16 ints
#define E_MIDX   7872      // 512 ints
#define E_TOTAL  8384      // floats = 33536 B

__global__ __launch_bounds__(256) void k_edge2(
    const int* __restrict__ adj, const int* __restrict__ mem,
    const float* __restrict__ bk,
    const float* __restrict__ b1,
    const float* __restrict__ W2, const float* __restrict__ b2)
{
    extern __shared__ float sm[];
    float* w1p    = sm + E_W1P;
    float* alpha  = sm + E_ALPHA;
    float* vc     = sm + E_VC;
    float* b1s    = sm + E_B1S;
    float* w2s    = sm + E_W2S;
    float* svals  = sm + E_SVALS;
    float* satt   = sm + E_SATT;
    int*   sadj   = (int*)(sm + E_SADJ);
    int*   midx   = (int*)(sm + E_MIDX);

    int tid = threadIdx.x, w = tid >> 5, lane = tid & 31;
    int bid = blockIdx.x;
    int tN  = (bid / NS) * NS;

    if (tid < EE) sadj[tid] = adj[bid * EE + tid];
    for (int q = tid; q < 512; q += 256) alpha[q] = d_alpha[bid * 512 + q];
    {
        const float4* src = (const float4*)d_w1p;
        float4* dst = (float4*)w1p;
        for (int idx = tid; idx < 1600; idx += 256) dst[idx] = src[idx];
    }
    if (tid < 200) { b1s[tid] = b1[tid]; w2s[tid] = W2[tid]; }
    __syncthreads();

    for (int q = tid; q < EE * KK; q += 256)
        midx[q] = tN + mem[(tN + sadj[q >> 5]) * KK + (q & 31)];
    __syncthreads();

    // fused gather + vc: warp w handles edges {w, w+8}; lane = d
    float bk0 = __ldg(bk);
#pragma unroll
    for (int eo = 0; eo < 2; eo++) {
        int e = w + eo * 8;
        float acc = bk0;
#pragma unroll
        for (int j = 0; j < 32; j++) {
            int row = midx[e * 32 + j];              // LDS broadcast
            float a = alpha[e * 32 + j];             // LDS broadcast
            acc = fmaf(a, d_pseq[row * 32 + lane], acc);
        }
        vc[e * 32 + lane] = acc;
    }
    __syncthreads();

    // ---- edge scores: 16 threads/edge; packed f32x2 over d ----
    {
        int e = tid >> 4, q = tid & 15;
        uint64_t vp[16];
#pragma unroll
        for (int d2 = 0; d2 < 16; d2++)
            vp[d2] = pk2(vc[e * 32 + 2 * d2], vc[e * 32 + 2 * d2 + 1]);
        const float* Grow = d_GP + (tN + sadj[e]) * GPW;
        const uint64_t* w1p64 = (const uint64_t*)w1p;
        float partial = 0.0f;
        for (int m = q; m < 200; m += 16) {
            uint64_t mac = pk2(b1s[m] + Grow[m], 0.0f);
#pragma unroll
            for (int d2 = 0; d2 < 16; d2++)
                ffma2(mac, vp[d2], w1p64[d2 * 200 + m]);
            partial = fmaf(w2s[m], fmaxf(hadd2(mac), 0.0f), partial);
        }
#pragma unroll
        for (int off = 8; off > 0; off >>= 1)
            partial += __shfl_xor_sync(0xffffffffu, partial, off);
        if (q == 0) svals[e] = partial + __ldg(b2);
    }
    __syncthreads();

    if (tid == 0) {
        float mx = svals[0];
#pragma unroll
        for (int e = 1; e < EE; e++) mx = fmaxf(mx, svals[e]);
        float s = 0.0f;
#pragma unroll
        for (int e = 0; e < EE; e++) { float v = __expf(svals[e] - mx); satt[e] = v; s += v; }
        float inv = 1.0f / s;
#pragma unroll
        for (int e = 0; e < EE; e++) satt[e] *= inv;
    }
    __syncthreads();

    if (tid < 32) {
        float acc = 0.0f;
#pragma unroll
        for (int e = 0; e < EE; e++) acc = fmaf(satt[e], vc[e * 32 + tid], acc);
        d_hgv[bid * HH + tid] = acc;
    }
    if (tid < 128) {
        float acc = 0.0f;
#pragma unroll
        for (int e = 0; e < EE; e++)
            acc = fmaf(satt[e], d_GP[(tN + sadj[e]) * GPW + 200 + tid], acc);
        d_hgP[bid * 128 + tid] = acc;
    }
}

// ===========================================================================
// K5: second LSTM + heads. Gates = hgP + Wih2a @ hgv (smem-staged) + Whh2 h.
// ===========================================================================
__global__ __launch_bounds__(128) void k_lstm2(
    const float* __restrict__ Wih2, const float* __restrict__ Whh2,
    const float* __restrict__ bih2, const float* __restrict__ bhh2,
    const float* __restrict__ Wf1, const float* __restrict__ bf1,
    const float* __restrict__ Wf2, const float* __restrict__ bf2,
    float* __restrict__ out)
{
    __shared__ float whs[128 * 33];
    __shared__ float wia[128 * 33];   // Wih2[:, :32], [g][l] stride 33
    int tid = threadIdx.x;
    for (int idx = tid; idx < 4096; idx += 128) {
        int g = idx >> 5, l = idx & 31;
        whs[g * 33 + l] = Whh2[idx];
        wia[g * 33 + l] = Wih2[g * ZDIM + l];
    }
    __syncthreads();

    int warp = (blockIdx.x * blockDim.x + tid) >> 5;
    int lane = tid & 31;
    if (warp >= NS) return;
    int n = warp;

    float bi = bih2[lane]      + bhh2[lane];
    float bf = bih2[32 + lane] + bhh2[32 + lane];
    float bg = bih2[64 + lane] + bhh2[64 + lane];
    float bo = bih2[96 + lane] + bhh2[96 + lane];

    float whi[32], whf[32], whg[32], who[32];
#pragma unroll
    for (int l = 0; l < 32; l++) {
        whi[l] = whs[lane * 33 + l];
        whf[l] = whs[(32 + lane) * 33 + l];
        whg[l] = whs[(64 + lane) * 33 + l];
        who[l] = whs[(96 + lane) * 33 + l];
    }

    float h = 0.0f, c = 0.0f;
#pragma unroll
    for (int t = 0; t < TT; t++) {
        int row = t * NS + n;
        const float* hp = d_hgP + row * 128;
        float hvv = d_hgv[row * HH + lane];
        float zi = bi + hp[lane];
        float zf = bf + hp[32 + lane];
        float zg = bg + hp[64 + lane];
        float zo = bo + hp[96 + lane];
#pragma unroll
        for (int l = 0; l < 32; l++) {
            float hl  = __shfl_sync(0xffffffffu, h,   l);
            float hvl = __shfl_sync(0xffffffffu, hvv, l);
            zi = fmaf(whi[l], hl, zi);
            zf = fmaf(whf[l], hl, zf);
            zg = fmaf(whg[l], hl, zg);
            zo = fmaf(who[l], hl, zo);
            zi = fmaf(wia[lane * 33 + l],        hvl, zi);
            zf = fmaf(wia[(32 + lane) * 33 + l], hvl, zf);
            zg = fmaf(wia[(64 + lane) * 33 + l], hvl, zg);
            zo = fmaf(wia[(96 + lane) * 33 + l], hvl, zo);
        }
        c = sigf(zf) * c + sigf(zi) * tanhf(zg);
        h = sigf(zo) * tanhf(c);
    }

    float f1a = bf1[lane], f1b = bf1[32 + lane];
#pragma unroll
    for (int l = 0; l < 32; l++) {
        float hl = __shfl_sync(0xffffffffu, h, l);
        f1a = fmaf(Wf1[lane * 32 + l], hl, f1a);
        f1b = fmaf(Wf1[(32 + lane) * 32 + l], hl, f1b);
    }
    float p0 = Wf2[lane] * f1a + Wf2[32 + lane] * f1b;
    float p1 = Wf2[64 + lane] * f1a + Wf2[96 + lane] * f1b;
#pragma unroll
    for (int off = 16; off > 0; off >>= 1) {
        p0 += __shfl_xor_sync(0xffffffffu, p0, off);
        p1 += __shfl_xor_sync(0xffffffffu, p1, off);
    }
    if (lane == 0) {
        out[n * 2]     = p0 + bf2[0];
        out[n * 2 + 1] = p1 + bf2[1];
    }
}

// ===========================================================================
extern "C" void kernel_launch(void* const* d_in, const int* in_sizes, int n_in,
                              void* d_out, int out_size)
{
    const float* prices    = (const float*)d_in[0];
    const float* node_embs = (const float*)d_in[1];
    const int*   adj       = (const int*)  d_in[2];
    const int*   mem       = (const int*)  d_in[3];
    const float* W_ih1 = (const float*)d_in[4];
    const float* W_hh1 = (const float*)d_in[5];
    const float* b_ih1 = (const float*)d_in[6];
    const float* b_hh1 = (const float*)d_in[7];
    const float* Wt    = (const float*)d_in[8];
    const float* bt    = (const float*)d_in[9];
    const float* wk    = (const float*)d_in[10];
    const float* bk    = (const float*)d_in[11];
    const float* W1    = (const float*)d_in[12];
    const float* b1    = (const float*)d_in[13];
    const float* W2    = (const float*)d_in[14];
    const float* b2    = (const float*)d_in[15];
    const float* W_ih2 = (const float*)d_in[16];
    const float* W_hh2 = (const float*)d_in[17];
    const float* b_ih2 = (const float*)d_in[18];
    const float* b_hh2 = (const float*)d_in[19];
    const float* Wf1   = (const float*)d_in[20];
    const float* bf1   = (const float*)d_in[21];
    const float* Wf2   = (const float*)d_in[22];
    const float* bf2   = (const float*)d_in[23];
    float* out = (float*)d_out;

    const int attn_smem = AT_TOTAL * 4;   // 59456 B
    const int edge_smem = E_TOTAL * 4;    // 33536 B
    cudaFuncSetAttribute(k_attn,  cudaFuncAttributeMaxDynamicSharedMemorySize, attn_smem);
    cudaFuncSetAttribute(k_edge2, cudaFuncAttributeMaxDynamicSharedMemorySize, edge_smem);

    k_lstm1<<<126, 128>>>(prices, W_ih1, W_hh1, b_ih1, b_hh1, W1);
    dim3 ggrid((TN + 63) / 64, (GPW + 63) / 64);
    k_gemm<<<ggrid, 256>>>(node_embs, W1, W_ih2);
    k_attn<<<NROWS / 64, 256, attn_smem>>>(adj, mem, Wt, bt, wk);
    k_edge2<<<TN, 256, edge_smem>>>(adj, mem, bk, b1, W2, b2);
    k_lstm2<<<125, 128>>>(W_ih2, W_hh2, b_ih2, b_hh2, Wf1, bf1, Wf2, bf2, out);
}

// round 11
// speedup vs baseline: 3.7159x; 1.6303x over previous
#include <cuda_runtime.h>
#include <cstdint>

// ---------------------------------------------------------------------------
// StockModel: T=4, N=500, E=16, K=32, H=32, D=768, ZD=800, EH=200
//
//  K1  k_lstm1: prices -> p_seq (T,N,32); block 125 packs W1a -> d_w1p
//  K2  k_mid2:  blocks [0,500): vertex-conv attention -> d_alpha
//               (cp.async double-buffered member-row pipeline, FFMA2 math)
//               blocks [500,692): GEMM GP = node_embs @ [W1b|Wih2b]
//  K3  k_edge2: per (t,n): fused gather+vc, scores (f32x2), att -> hgv,hgP
//  K4  k_lstm2: gates = hgP + Wih2a@hgv (smem) -> h_n -> out (N,2)
// ---------------------------------------------------------------------------

#define TT 4
#define NS 500
#define EE 16
#define KK 32
#define HH 32
#define DD 768
#define ZDIM 800
#define GPW 328
#define TN 2000
#define NROWS (TN * EE)

__device__ float d_pseq[TN * HH];
__device__ float d_GP[TN * GPW];
__device__ float d_alpha[NROWS * KK];
__device__ float d_hgv[TN * HH];
__device__ float d_hgP[TN * 128];
__device__ float d_w1p[32 * 200];   // W1[:, :32] pair-packed

__device__ __forceinline__ float sigf(float x) { return 1.0f / (1.0f + __expf(-x)); }

// ---- packed f32x2 helpers (sm_100+) ----
__device__ __forceinline__ uint64_t pk2(float lo, float hi) {
    uint64_t r; asm("mov.b64 %0, {%1, %2};" : "=l"(r) : "f"(lo), "f"(hi)); return r;
}
__device__ __forceinline__ void ffma2(uint64_t& d, uint64_t a, uint64_t b) {
    asm("fma.rn.f32x2 %0, %1, %2, %3;" : "=l"(d) : "l"(a), "l"(b), "l"(d));
}
__device__ __forceinline__ float hadd2(uint64_t v) {
    float lo, hi; asm("mov.b64 {%0, %1}, %2;" : "=f"(lo), "=f"(hi) : "l"(v));
    return lo + hi;
}

// ---- cp.async helpers ----
__device__ __forceinline__ void cp16(uint32_t dst, const void* src) {
    asm volatile("cp.async.cg.shared.global [%0], [%1], 16;" :: "r"(dst), "l"(src) : "memory");
}
__device__ __forceinline__ void cp_commit() { asm volatile("cp.async.commit_group;" ::: "memory"); }
template<int N> __device__ __forceinline__ void cp_wait() {
    asm volatile("cp.async.wait_group %0;" :: "n"(N) : "memory");
}

// ===========================================================================
// K1: price LSTM (blocks 0..124), W1a pair-pack (block 125).
// ===========================================================================
__global__ __launch_bounds__(128) void k_lstm1(
    const float* __restrict__ prices,
    const float* __restrict__ Wih, const float* __restrict__ Whh,
    const float* __restrict__ bih, const float* __restrict__ bhh,
    const float* __restrict__ W1)
{
    int tid = threadIdx.x;
    if (blockIdx.x == 125) {
        for (int idx = tid; idx < 6400; idx += 128) {
            int pairIdx = idx >> 1, c = idx & 1;
            int d2 = pairIdx / 200, m = pairIdx % 200;
            d_w1p[idx] = W1[m * ZDIM + 2 * d2 + c];
        }
        return;
    }

    __shared__ float whs[128 * 33];
    for (int idx = tid; idx < 4096; idx += 128)
        whs[(idx >> 5) * 33 + (idx & 31)] = Whh[idx];
    __syncthreads();

    int warp = (blockIdx.x * blockDim.x + tid) >> 5;
    int lane = tid & 31;
    if (warp >= NS) return;
    int n = warp;

    float wxi = Wih[lane],      wxf = Wih[32 + lane];
    float wxg = Wih[64 + lane], wxo = Wih[96 + lane];
    float bi = bih[lane]      + bhh[lane];
    float bf = bih[32 + lane] + bhh[32 + lane];
    float bg = bih[64 + lane] + bhh[64 + lane];
    float bo = bih[96 + lane] + bhh[96 + lane];

    float whi[32], whf[32], whg[32], who[32];
#pragma unroll
    for (int l = 0; l < 32; l++) {
        whi[l] = whs[lane * 33 + l];
        whf[l] = whs[(32 + lane) * 33 + l];
        whg[l] = whs[(64 + lane) * 33 + l];
        who[l] = whs[(96 + lane) * 33 + l];
    }

    float h = 0.0f, c = 0.0f;
#pragma unroll
    for (int t = 0; t < TT; t++) {
        float x = prices[t * NS + n];
        float zi = fmaf(wxi, x, bi), zf = fmaf(wxf, x, bf);
        float zg = fmaf(wxg, x, bg), zo = fmaf(wxo, x, bo);
#pragma unroll
        for (int l = 0; l < 32; l++) {
            float hl = __shfl_sync(0xffffffffu, h, l);
            zi = fmaf(whi[l], hl, zi);
            zf = fmaf(whf[l], hl, zf);
            zg = fmaf(whg[l], hl, zg);
            zo = fmaf(who[l], hl, zo);
        }
        c = sigf(zf) * c + sigf(zi) * tanhf(zg);
        h = sigf(zo) * tanhf(c);
        d_pseq[(t * NS + n) * HH + lane] = h;
    }
}

// ===========================================================================
// K2: fused attn (blocks 0..499) + GEMM (blocks 500..691).
// attn smem layout (floats):
#define AT2_WT    0        // 4096  wt[q][j][d] (single buffer, sync cp.async)
#define AT2_BT    4096     // 1024  all of bt
#define AT2_WK    5120     // 32
#define AT2_ADJ   5152     // 64 ints
#define AT2_TN    5216     // 64 ints
#define AT2_MIDX  5280     // 2048 ints
#define AT2_SROWS 7328     // 2 x 256 x 36 = 18432 (row stride 36: 16B-aligned,
                           //   conflict-free float4 consume; red overlay at end)
#define AT2_TOTAL 25760    // = 103040 bytes
#define ATTN_BLKS 500
// ===========================================================================
__global__ __launch_bounds__(256) void k_mid2(
    const int* __restrict__ adj, const int* __restrict__ mem,
    const float* __restrict__ Wt, const float* __restrict__ bt,
    const float* __restrict__ wk,
    const float* __restrict__ ne,
    const float* __restrict__ W1,
    const float* __restrict__ Wih2)
{
    extern __shared__ float dyn[];
    int tid = threadIdx.x;

    if (blockIdx.x < ATTN_BLKS) {
        float* btA   = dyn + AT2_BT;
        float* wkA   = dyn + AT2_WK;
        int*   sadj  = (int*)(dyn + AT2_ADJ);
        int*   stN   = (int*)(dyn + AT2_TN);
        int*   midx  = (int*)(dyn + AT2_MIDX);
        uint32_t sbase = (uint32_t)__cvta_generic_to_shared(dyn);

        int rloc = tid & 63, q = tid >> 6;
        int w = tid >> 5, lane = tid & 31;
        int cg = lane >> 3, cb = lane & 7;

        if (tid < 64) {
            int row = blockIdx.x * 64 + tid;
            int tn = row >> 4, e = row & 15;
            sadj[tid] = adj[tn * EE + e];
            stN[tid]  = (tn / NS) * NS;
        }
        for (int idx = tid; idx < 1024; idx += 256) btA[idx] = bt[idx];
        if (tid < 32) wkA[tid] = wk[tid];
        __syncthreads();
        for (int idx = tid; idx < 2048; idx += 256) {
            int r = idx >> 5, i = idx & 31;
            midx[idx] = stN[r] + mem[(stN[r] + sadj[r]) * KK + i];
        }
        __syncthreads();

        // prologue: stage srows for step 0 into buffer 0
        {
#pragma unroll
            for (int rr = 0; rr < 8; rr++) {
                int r = w * 32 + rr * 4 + cg;
                int rl = r & 63, qq2 = r >> 6;
                int mrow = midx[rl * 32 + 8 * qq2];     // s = 0
                cp16(sbase + (AT2_SROWS + r * 36 + cb * 4) * 4,
                     d_pseq + mrow * 32 + cb * 4);
            }
            cp_commit();
        }

        float acc[32];
#pragma unroll
        for (int j = 0; j < 32; j++) acc[j] = 0.0f;

        for (int s = 0; s < 8; s++) {
            int i = 8 * q + s;
            // wt(s): synchronous group (L2-resident, cheap)
            {
                const float* wsrc = Wt + i * 1024 + rloc * 16;
                uint32_t wd = sbase + (AT2_WT + q * 1024 + rloc * 16) * 4;
                cp16(wd, wsrc); cp16(wd + 16, wsrc + 4);
                cp16(wd + 32, wsrc + 8); cp16(wd + 48, wsrc + 12);
                cp_commit();
            }
            // srows(s+1): pipelined group
            if (s < 7) {
                int bsel = (s + 1) & 1;
#pragma unroll
                for (int rr = 0; rr < 8; rr++) {
                    int r = w * 32 + rr * 4 + cg;
                    int rl = r & 63, qq2 = r >> 6;
                    int mrow = midx[rl * 32 + 8 * qq2 + s + 1];
                    cp16(sbase + (AT2_SROWS + bsel * 9216 + r * 36 + cb * 4) * 4,
                         d_pseq + mrow * 32 + cb * 4);
                }
                cp_commit();
                cp_wait<1>();          // srows(s) + wt(s) landed; srows(s+1) in flight
            } else {
                cp_wait<0>();
            }
            __syncthreads();

            // consume: full softmax row in registers
            uint64_t rgp[16];
            {
                const float4* basep =
                    (const float4*)(dyn + AT2_SROWS + (s & 1) * 9216 + (q * 64 + rloc) * 36);
#pragma unroll
                for (int u = 0; u < 8; u++) {
                    float4 rv = basep[u];
                    rgp[2 * u]     = pk2(rv.x, rv.y);
                    rgp[2 * u + 1] = pk2(rv.z, rv.w);
                }
            }
            const float* wb = dyn + AT2_WT + q * 1024;
            float em[32];
            float srow = 0.0f;
#pragma unroll
            for (int j = 0; j < 32; j++) {
                const ulonglong2* w2p = (const ulonglong2*)(wb + j * 32);
                uint64_t mac = pk2(btA[i * 32 + j], 0.0f);
#pragma unroll
                for (int u = 0; u < 8; u++) {
                    ulonglong2 wv = w2p[u];
                    ffma2(mac, wv.x, rgp[2 * u]);
                    ffma2(mac, wv.y, rgp[2 * u + 1]);
                }
                float ev = __expf(hadd2(mac));   // |m| small: no max-subtraction needed
                em[j] = ev;
                srow += ev;
            }
            float f = __fdividef(wkA[i], srow);
#pragma unroll
            for (int j = 0; j < 32; j++) acc[j] = fmaf(em[j], f, acc[j]);
            __syncthreads();   // all readers done: buffers free for next iter's writes
        }

        // cross-quarter reduction (red overlays srows)
        float* red = dyn + AT2_SROWS;
        {
            float4* rp = (float4*)(red + q * 2048 + rloc * 32);
#pragma unroll
            for (int u = 0; u < 8; u++)
                rp[u] = make_float4(acc[u * 4], acc[u * 4 + 1], acc[u * 4 + 2], acc[u * 4 + 3]);
        }
        __syncthreads();
        for (int o = tid; o < 512; o += 256) {
            const float4 v0 = *(const float4*)(red + o * 4);
            const float4 v1 = *(const float4*)(red + 2048 + o * 4);
            const float4 v2 = *(const float4*)(red + 4096 + o * 4);
            const float4 v3 = *(const float4*)(red + 6144 + o * 4);
            float4 v = make_float4(v0.x + v1.x + v2.x + v3.x,
                                   v0.y + v1.y + v2.y + v3.y,
                                   v0.z + v1.z + v2.z + v3.z,
                                   v0.w + v1.w + v2.w + v3.w);
            *(float4*)(d_alpha + blockIdx.x * 2048 + o * 4) = v;
        }
    } else {
        // -------- GEMM part: GP = ne(2000x768) @ B(768x328) --------
        float* As = dyn;          // 16*64
        float* Bs = dyn + 1024;   // 16*64
        int bx = blockIdx.x - ATTN_BLKS;
        int rb = (bx & 31) * 64, cb2 = (bx >> 5) * 64;
        int tx = tid & 15, ty = tid >> 4;
        int lm = tid >> 2;
        int lk = (tid & 3) * 4;

        float acc[4][4];
#pragma unroll
        for (int r = 0; r < 4; r++)
#pragma unroll
            for (int cq = 0; cq < 4; cq++) acc[r][cq] = 0.0f;

        int arow = rb + lm;
        int bcol = cb2 + lm;

        for (int k0 = 0; k0 < DD; k0 += 16) {
            float4 av = make_float4(0.f, 0.f, 0.f, 0.f);
            if (arow < TN) av = *(const float4*)(ne + arow * DD + k0 + lk);
            float4 bv = make_float4(0.f, 0.f, 0.f, 0.f);
            if (bcol < 200)      bv = *(const float4*)(W1 + bcol * ZDIM + 32 + k0 + lk);
            else if (bcol < GPW) bv = *(const float4*)(Wih2 + (bcol - 200) * ZDIM + 32 + k0 + lk);
            As[(lk + 0) * 64 + lm] = av.x; As[(lk + 1) * 64 + lm] = av.y;
            As[(lk + 2) * 64 + lm] = av.z; As[(lk + 3) * 64 + lm] = av.w;
            Bs[(lk + 0) * 64 + lm] = bv.x; Bs[(lk + 1) * 64 + lm] = bv.y;
            Bs[(lk + 2) * 64 + lm] = bv.z; Bs[(lk + 3) * 64 + lm] = bv.w;
            __syncthreads();
#pragma unroll
            for (int k = 0; k < 16; k++) {
                float4 a4 = *(const float4*)(&As[k * 64 + ty * 4]);
                float4 b4 = *(const float4*)(&Bs[k * 64 + tx * 4]);
                float ar[4] = {a4.x, a4.y, a4.z, a4.w};
                float br[4] = {b4.x, b4.y, b4.z, b4.w};
#pragma unroll
                for (int r = 0; r < 4; r++)
#pragma unroll
                    for (int cq = 0; cq < 4; cq++)
                        acc[r][cq] = fmaf(ar[r], br[cq], acc[r][cq]);
            }
            __syncthreads();
        }
#pragma unroll
        for (int r = 0; r < 4; r++) {
            int rrow = rb + ty * 4 + r;
            int col = cb2 + tx * 4;
            if (rrow < TN && col < GPW) {
                float4 v = make_float4(acc[r][0], acc[r][1], acc[r][2], acc[r][3]);
                *(float4*)(d_GP + rrow * GPW + col) = v;
            }
        }
    }
}

// ===========================================================================
// K3: per (t,n): fused gather+vc, scores (f32x2), att, hgv+hgP. smem 33.5KB.
// ===========================================================================
#define E_W1P    0         // 6400
#define E_ALPHA  6400      // 512
#define E_VC     6912      // 512
#define E_B1S    7424      // 200
#define E_W2S    7624      // 200
#define E_SVALS  7824      // 16
#define E_SATT   7840      // 16
#define E_SADJ   7856      // 16 ints
#define E_MIDX   7872      // 512 ints
#define E_TOTAL  8384      // floats = 33536 B

__global__ __launch_bounds__(256) void k_edge2(
    const int* __restrict__ adj, const int* __restrict__ mem,
    const float* __restrict__ bk,
    const float* __restrict__ b1,
    const float* __restrict__ W2, const float* __restrict__ b2)
{
    extern __shared__ float sm[];
    float* w1p    = sm + E_W1P;
    float* alpha  = sm + E_ALPHA;
    float* vc     = sm + E_VC;
    float* b1s    = sm + E_B1S;
    float* w2s    = sm + E_W2S;
    float* svals  = sm + E_SVALS;
    float* satt   = sm + E_SATT;
    int*   sadj   = (int*)(sm + E_SADJ);
    int*   midx   = (int*)(sm + E_MIDX);

    int tid = threadIdx.x, w = tid >> 5, lane = tid & 31;
    int bid = blockIdx.x;
    int tN  = (bid / NS) * NS;

    if (tid < EE) sadj[tid] = adj[bid * EE + tid];
    for (int q = tid; q < 512; q += 256) alpha[q] = d_alpha[bid * 512 + q];
    {
        const float4* src = (const float4*)d_w1p;
        float4* dst = (float4*)w1p;
        for (int idx = tid; idx < 1600; idx += 256) dst[idx] = src[idx];
    }
    if (tid < 200) { b1s[tid] = b1[tid]; w2s[tid] = W2[tid]; }
    __syncthreads();

    for (int q = tid; q < EE * KK; q += 256)
        midx[q] = tN + mem[(tN + sadj[q >> 5]) * KK + (q & 31)];
    __syncthreads();

    // fused gather + vc: warp w handles edges {w, w+8}; lane = d
    float bk0 = __ldg(bk);
#pragma unroll
    for (int eo = 0; eo < 2; eo++) {
        int e = w + eo * 8;
        float acc = bk0;
#pragma unroll
        for (int j = 0; j < 32; j++) {
            int row = midx[e * 32 + j];
            float a = alpha[e * 32 + j];
            acc = fmaf(a, d_pseq[row * 32 + lane], acc);
        }
        vc[e * 32 + lane] = acc;
    }
    __syncthreads();

    // ---- edge scores: 16 threads/edge; packed f32x2 over d ----
    {
        int e = tid >> 4, q = tid & 15;
        uint64_t vp[16];
#pragma unroll
        for (int d2 = 0; d2 < 16; d2++)
            vp[d2] = pk2(vc[e * 32 + 2 * d2], vc[e * 32 + 2 * d2 + 1]);
        const float* Grow = d_GP + (tN + sadj[e]) * GPW;
        const uint64_t* w1p64 = (const uint64_t*)w1p;
        float partial = 0.0f;
        for (int m = q; m < 200; m += 16) {
            uint64_t mac = pk2(b1s[m] + Grow[m], 0.0f);
#pragma unroll
            for (int d2 = 0; d2 < 16; d2++)
                ffma2(mac, vp[d2], w1p64[d2 * 200 + m]);
            partial = fmaf(w2s[m], fmaxf(hadd2(mac), 0.0f), partial);
        }
#pragma unroll
        for (int off = 8; off > 0; off >>= 1)
            partial += __shfl_xor_sync(0xffffffffu, partial, off);
        if (q == 0) svals[e] = partial + __ldg(b2);
    }
    __syncthreads();

    if (tid == 0) {
        float mx = svals[0];
#pragma unroll
        for (int e = 1; e < EE; e++) mx = fmaxf(mx, svals[e]);
        float s = 0.0f;
#pragma unroll
        for (int e = 0; e < EE; e++) { float v = __expf(svals[e] - mx); satt[e] = v; s += v; }
        float inv = 1.0f / s;
#pragma unroll
        for (int e = 0; e < EE; e++) satt[e] *= inv;
    }
    __syncthreads();

    if (tid < 32) {
        float acc = 0.0f;
#pragma unroll
        for (int e = 0; e < EE; e++) acc = fmaf(satt[e], vc[e * 32 + tid], acc);
        d_hgv[bid * HH + tid] = acc;
    }
    if (tid < 128) {
        float acc = 0.0f;
#pragma unroll
        for (int e = 0; e < EE; e++)
            acc = fmaf(satt[e], d_GP[(tN + sadj[e]) * GPW + 200 + tid], acc);
        d_hgP[bid * 128 + tid] = acc;
    }
}

// ===========================================================================
// K4: second LSTM + heads. Gates = hgP + Wih2a @ hgv (smem-staged) + Whh2 h.
// ===========================================================================
__global__ __launch_bounds__(128) void k_lstm2(
    const float* __restrict__ Wih2, const float* __restrict__ Whh2,
    const float* __restrict__ bih2, const float* __restrict__ bhh2,
    const float* __restrict__ Wf1, const float* __restrict__ bf1,
    const float* __restrict__ Wf2, const float* __restrict__ bf2,
    float* __restrict__ out)
{
    __shared__ float whs[128 * 33];
    __shared__ float wia[128 * 33];
    int tid = threadIdx.x;
    for (int idx = tid; idx < 4096; idx += 128) {
        int g = idx >> 5, l = idx & 31;
        whs[g * 33 + l] = Whh2[idx];
        wia[g * 33 + l] = Wih2[g * ZDIM + l];
    }
    __syncthreads();

    int warp = (blockIdx.x * blockDim.x + tid) >> 5;
    int lane = tid & 31;
    if (warp >= NS) return;
    int n = warp;

    float bi = bih2[lane]      + bhh2[lane];
    float bf = bih2[32 + lane] + bhh2[32 + lane];
    float bg = bih2[64 + lane] + bhh2[64 + lane];
    float bo = bih2[96 + lane] + bhh2[96 + lane];

    float whi[32], whf[32], whg[32], who[32];
#pragma unroll
    for (int l = 0; l < 32; l++) {
        whi[l] = whs[lane * 33 + l];
        whf[l] = whs[(32 + lane) * 33 + l];
        whg[l] = whs[(64 + lane) * 33 + l];
        who[l] = whs[(96 + lane) * 33 + l];
    }

    float h = 0.0f, c = 0.0f;
#pragma unroll
    for (int t = 0; t < TT; t++) {
        int row = t * NS + n;
        const float* hp = d_hgP + row * 128;
        float hvv = d_hgv[row * HH + lane];
        float zi = bi + hp[lane];
        float zf = bf + hp[32 + lane];
        float zg = bg + hp[64 + lane];
        float zo = bo + hp[96 + lane];
#pragma unroll
        for (int l = 0; l < 32; l++) {
            float hl  = __shfl_sync(0xffffffffu, h,   l);
            float hvl = __shfl_sync(0xffffffffu, hvv, l);
            zi = fmaf(whi[l], hl, zi);
            zf = fmaf(whf[l], hl, zf);
            zg = fmaf(whg[l], hl, zg);
            zo = fmaf(who[l], hl, zo);
            zi = fmaf(wia[lane * 33 + l],        hvl, zi);
            zf = fmaf(wia[(32 + lane) * 33 + l], hvl, zf);
            zg = fmaf(wia[(64 + lane) * 33 + l], hvl, zg);
            zo = fmaf(wia[(96 + lane) * 33 + l], hvl, zo);
        }
        c = sigf(zf) * c + sigf(zi) * tanhf(zg);
        h = sigf(zo) * tanhf(c);
    }

    float f1a = bf1[lane], f1b = bf1[32 + lane];
#pragma unroll
    for (int l = 0; l < 32; l++) {
        float hl = __shfl_sync(0xffffffffu, h, l);
        f1a = fmaf(Wf1[lane * 32 + l], hl, f1a);
        f1b = fmaf(Wf1[(32 + lane) * 32 + l], hl, f1b);
    }
    float p0 = Wf2[lane] * f1a + Wf2[32 + lane] * f1b;
    float p1 = Wf2[64 + lane] * f1a + Wf2[96 + lane] * f1b;
#pragma unroll
    for (int off = 16; off > 0; off >>= 1) {
        p0 += __shfl_xor_sync(0xffffffffu, p0, off);
        p1 += __shfl_xor_sync(0xffffffffu, p1, off);
    }
    if (lane == 0) {
        out[n * 2]     = p0 + bf2[0];
        out[n * 2 + 1] = p1 + bf2[1];
    }
}

// ===========================================================================
extern "C" void kernel_launch(void* const* d_in, const int* in_sizes, int n_in,
                              void* d_out, int out_size)
{
    const float* prices    = (const float*)d_in[0];
    const float* node_embs = (const float*)d_in[1];
    const int*   adj       = (const int*)  d_in[2];
    const int*   mem       = (const int*)  d_in[3];
    const float* W_ih1 = (const float*)d_in[4];
    const float* W_hh1 = (const float*)d_in[5];
    const float* b_ih1 = (const float*)d_in[6];
    const float* b_hh1 = (const float*)d_in[7];
    const float* Wt    = (const float*)d_in[8];
    const float* bt    = (const float*)d_in[9];
    const float* wk    = (const float*)d_in[10];
    const float* bk    = (const float*)d_in[11];
    const float* W1    = (const float*)d_in[12];
    const float* b1    = (const float*)d_in[13];
    const float* W2    = (const float*)d_in[14];
    const float* b2    = (const float*)d_in[15];
    const float* W_ih2 = (const float*)d_in[16];
    const float* W_hh2 = (const float*)d_in[17];
    const float* b_ih2 = (const float*)d_in[18];
    const float* b_hh2 = (const float*)d_in[19];
    const float* Wf1   = (const float*)d_in[20];
    const float* bf1   = (const float*)d_in[21];
    const float* Wf2   = (const float*)d_in[22];
    const float* bf2   = (const float*)d_in[23];
    float* out = (float*)d_out;

    const int mid_smem  = AT2_TOTAL * 4;  // 103040 B -> 2 blocks/SM
    const int edge_smem = E_TOTAL * 4;    // 33536 B  -> 4 blocks/SM
    cudaFuncSetAttribute(k_mid2,  cudaFuncAttributeMaxDynamicSharedMemorySize, mid_smem);
    cudaFuncSetAttribute(k_edge2, cudaFuncAttributeMaxDynamicSharedMemorySize, edge_smem);

    k_lstm1<<<126, 128>>>(prices, W_ih1, W_hh1, b_ih1, b_hh1, W1);
    k_mid2<<<ATTN_BLKS + 192, 256, mid_smem>>>(adj, mem, Wt, bt, wk, node_embs, W1, W_ih2);
    k_edge2<<<TN, 256, edge_smem>>>(adj, mem, bk, b1, W2, b2);
    k_lstm2<<<125, 128>>>(W_ih2, W_hh2, b_ih2, b_hh2, Wf1, bf1, Wf2, bf2, out);
}